// round 2
// baseline (speedup 1.0000x reference)
#include <cuda_runtime.h>
#include <cuda_bf16.h>

// ---------------- problem constants ----------------
#define BSZ   8
#define CIN   256
#define NYv   80
#define NXv   80
#define CC    256
#define HW    (NYv * NXv)        // 6400
#define NPTS  16384
#define KD    (CC * 9)           // 2304
#define NOUT  85                 // 4 reg + 1 obj + 80 cls

// ---------------- scratch (no cudaMalloc allowed) ----------------
__device__ float g_stem[(size_t)BSZ * CC * HW];     // 52.4 MB
__device__ float g_feat[(size_t)2 * NPTS * CC];     // 33.5 MB (set0=cls, set1=reg)
__device__ int   g_sb[NPTS], g_sy[NPTS], g_sx[NPTS];

__device__ __forceinline__ float silu(float v) {
    return v * (1.0f / (1.0f + __expf(-v)));
}

// ============================================================
// Kernel 0: decode indices. Harness may deliver them as int64
// (reference dtype) or down-converted int32. Detect: int64 (LE)
// has zero high words at every odd 32-bit position; int32 data has
// random bi/yi values there (12-word check => ~1e-17 false positive).
// ============================================================
__global__ void decode_indices(const int* __restrict__ idx32) {
    int n = blockIdx.x * blockDim.x + threadIdx.x;
    if (n >= NPTS) return;
    bool is64 = true;
    #pragma unroll
    for (int k = 1; k < 24; k += 2) is64 = is64 && (idx32[k] == 0);
    int bi, yi, xi;
    if (is64) {
        bi = idx32[6 * n + 0];
        yi = idx32[6 * n + 2];
        xi = idx32[6 * n + 4];
    } else {
        bi = idx32[3 * n + 0];
        yi = idx32[3 * n + 1];
        xi = idx32[3 * n + 2];
    }
    g_sb[n] = bi; g_sy[n] = yi; g_sx[n] = xi;
}

// ---------------- tiled SGEMM params ----------------
#define BM 128
#define BN 128
#define BK 8
#define TM 8
#define TN 8

// ============================================================
// Kernel 1: stem = silu( W[256,256] @ x[b][256,6400] + b )
// ============================================================
__global__ __launch_bounds__(256) void stem_kernel(
    const float* __restrict__ x, const float* __restrict__ w,
    const float* __restrict__ bias)
{
    __shared__ float As[BK][BM];   // W tile [k][o]
    __shared__ float Bs[BK][BN];   // x tile [k][p]

    const int b  = blockIdx.z;
    const int o0 = blockIdx.y * BM;
    const int p0 = blockIdx.x * BN;
    const int tid = threadIdx.x;
    const int tr = tid / 16, tc = tid % 16;
    const float* xb = x + (size_t)b * CIN * HW;

    float acc[TM][TN] = {};

    for (int k0 = 0; k0 < CIN; k0 += BK) {
        #pragma unroll
        for (int j = 0; j < 4; j++) {
            int id  = tid + 256 * j;
            int row = id >> 3, col = id & 7;
            As[col][row] = w[(size_t)(o0 + row) * CIN + k0 + col];
        }
        #pragma unroll
        for (int j = 0; j < 4; j++) {
            int id  = tid + 256 * j;
            int row = id >> 7, col = id & 127;
            Bs[row][col] = xb[(size_t)(k0 + row) * HW + p0 + col];
        }
        __syncthreads();
        #pragma unroll
        for (int kk = 0; kk < BK; kk++) {
            float a[TM], bb[TN];
            #pragma unroll
            for (int i = 0; i < TM; i++) a[i]  = As[kk][tr * TM + i];
            #pragma unroll
            for (int j = 0; j < TN; j++) bb[j] = Bs[kk][tc * TN + j];
            #pragma unroll
            for (int i = 0; i < TM; i++)
                #pragma unroll
                for (int j = 0; j < TN; j++)
                    acc[i][j] = fmaf(a[i], bb[j], acc[i][j]);
        }
        __syncthreads();
    }

    #pragma unroll
    for (int i = 0; i < TM; i++) {
        int o = o0 + tr * TM + i;
        float bv = bias[o];
        #pragma unroll
        for (int j = 0; j < TN; j++) {
            int p = p0 + tc * TN + j;
            g_stem[((size_t)b * CC + o) * HW + p] = silu(acc[i][j] + bv);
        }
    }
}

// ============================================================
// Kernel 2: feat[set] = silu( pf @ conv_w[set]^T + conv_b[set] )
//   pf gathered on the fly from g_stem (zero-padded 3x3).
// ============================================================
__global__ __launch_bounds__(256) void conv_kernel(
    const float* __restrict__ w_cls, const float* __restrict__ b_cls,
    const float* __restrict__ w_reg, const float* __restrict__ b_reg)
{
    __shared__ float As[BK][BM];       // pf tile [k][n]
    __shared__ float Bs[BK][BN];       // w tile  [k][o]
    __shared__ int sb[BM], sy[BM], sx[BM];

    const int set = blockIdx.z;
    const float* w    = set ? w_reg : w_cls;
    const float* bias = set ? b_reg : b_cls;
    const int n0 = blockIdx.x * BM;
    const int o0 = blockIdx.y * BN;
    const int tid = threadIdx.x;

    if (tid < BM) {
        sb[tid] = g_sb[n0 + tid];
        sy[tid] = g_sy[n0 + tid];
        sx[tid] = g_sx[n0 + tid];
    }
    __syncthreads();

    const int tr = tid / 16, tc = tid % 16;
    float acc[TM][TN] = {};

    for (int k0 = 0; k0 < KD; k0 += BK) {
        #pragma unroll
        for (int j = 0; j < 4; j++) {
            int id = tid + 256 * j;
            int r  = id >> 3, kc = id & 7;
            int k  = k0 + kc;
            int c   = k / 9;
            int rem = k - c * 9;
            int kh  = rem / 3;
            int kw  = rem - kh * 3;
            int y  = sy[r] + kh - 1;
            int xq = sx[r] + kw - 1;
            float v = 0.0f;
            if ((unsigned)y < NYv && (unsigned)xq < NXv)
                v = g_stem[(((size_t)sb[r] * CC + c) * NYv + y) * NXv + xq];
            As[kc][r] = v;
        }
        #pragma unroll
        for (int j = 0; j < 4; j++) {
            int id  = tid + 256 * j;
            int row = id >> 3, col = id & 7;
            Bs[col][row] = w[(size_t)(o0 + row) * KD + k0 + col];
        }
        __syncthreads();
        #pragma unroll
        for (int kk = 0; kk < BK; kk++) {
            float a[TM], bb[TN];
            #pragma unroll
            for (int i = 0; i < TM; i++) a[i]  = As[kk][tr * TM + i];
            #pragma unroll
            for (int j = 0; j < TN; j++) bb[j] = Bs[kk][tc * TN + j];
            #pragma unroll
            for (int i = 0; i < TM; i++)
                #pragma unroll
                for (int j = 0; j < TN; j++)
                    acc[i][j] = fmaf(a[i], bb[j], acc[i][j]);
        }
        __syncthreads();
    }

    #pragma unroll
    for (int j = 0; j < TN; j++) {
        int o = o0 + tc * TN + j;
        float bv = bias[o];
        #pragma unroll
        for (int i = 0; i < TM; i++) {
            int n = n0 + tr * TM + i;
            g_feat[((size_t)set * NPTS + n) * CC + o] = silu(acc[i][j] + bv);
        }
    }
}

// ============================================================
// Kernel 3: prediction heads + interleave. out[n] = [reg(4), obj(1), cls(80)]
// ============================================================
__global__ __launch_bounds__(256) void pred_kernel(
    const float* __restrict__ cw, const float* __restrict__ cb,
    const float* __restrict__ rw, const float* __restrict__ rb,
    const float* __restrict__ ow, const float* __restrict__ ob,
    float* __restrict__ out)
{
    const int gwarp = (blockIdx.x * blockDim.x + threadIdx.x) >> 5;
    const int lane  = threadIdx.x & 31;
    const int RPW = 4;
    const int n0 = gwarp * RPW;
    if (n0 >= NPTS) return;

    float cf[RPW][8], rf[RPW][8];
    #pragma unroll
    for (int r = 0; r < RPW; r++)
        #pragma unroll
        for (int i = 0; i < 8; i++) {
            cf[r][i] = g_feat[(size_t)(n0 + r) * CC + lane + 32 * i];
            rf[r][i] = g_feat[(size_t)(NPTS + n0 + r) * CC + lane + 32 * i];
        }

    for (int o = 0; o < NOUT; o++) {
        const float* w; float bv; bool useReg;
        if (o < 4)       { w = rw + (size_t)o * CC;       bv = rb[o];     useReg = true;  }
        else if (o == 4) { w = ow;                        bv = ob[0];     useReg = true;  }
        else             { w = cw + (size_t)(o - 5) * CC; bv = cb[o - 5]; useReg = false; }

        float wv[8];
        #pragma unroll
        for (int i = 0; i < 8; i++) wv[i] = w[lane + 32 * i];

        #pragma unroll
        for (int r = 0; r < RPW; r++) {
            float s = 0.0f;
            #pragma unroll
            for (int i = 0; i < 8; i++)
                s = fmaf(useReg ? rf[r][i] : cf[r][i], wv[i], s);
            #pragma unroll
            for (int off = 16; off > 0; off >>= 1)
                s += __shfl_down_sync(0xffffffffu, s, off);
            if (lane == 0) out[(size_t)(n0 + r) * NOUT + o] = s + bv;
        }
    }
}

// ============================================================
// launch
// ============================================================
extern "C" void kernel_launch(void* const* d_in, const int* in_sizes, int n_in,
                              void* d_out, int out_size)
{
    const float* x           = (const float*)d_in[0];
    const int*   indices32   = (const int*)d_in[1];
    const float* stem_w      = (const float*)d_in[2];
    const float* stem_b      = (const float*)d_in[3];
    const float* cls_conv_w  = (const float*)d_in[4];
    const float* cls_conv_b  = (const float*)d_in[5];
    const float* reg_conv_w  = (const float*)d_in[6];
    const float* reg_conv_b  = (const float*)d_in[7];
    const float* cls_pred_w  = (const float*)d_in[8];
    const float* cls_pred_b  = (const float*)d_in[9];
    const float* reg_pred_w  = (const float*)d_in[10];
    const float* reg_pred_b  = (const float*)d_in[11];
    const float* obj_pred_w  = (const float*)d_in[12];
    const float* obj_pred_b  = (const float*)d_in[13];
    float* out = (float*)d_out;

    decode_indices<<<NPTS / 256, 256>>>(indices32);

    dim3 g1(HW / BN, CC / BM, BSZ);            // 50 x 2 x 8
    stem_kernel<<<g1, 256>>>(x, stem_w, stem_b);

    dim3 g2(NPTS / BM, CC / BN, 2);            // 128 x 2 x 2
    conv_kernel<<<g2, 256>>>(cls_conv_w, cls_conv_b, reg_conv_w, reg_conv_b);

    int warps = NPTS / 4;
    int threads = warps * 32;
    pred_kernel<<<threads / 256, 256>>>(cls_pred_w, cls_pred_b,
                                        reg_pred_w, reg_pred_b,
                                        obj_pred_w, obj_pred_b, out);
}

// round 5
// speedup vs baseline: 2.9984x; 2.9984x over previous
#include <cuda_runtime.h>
#include <cuda_bf16.h>
#include <cuda_pipeline.h>
#include <stdint.h>

// ---------------- problem constants ----------------
#define BSZ   8
#define CIN   256
#define NYv   80
#define NXv   80
#define CC    256
#define HW    (NYv * NXv)        // 6400
#define NPIX  (BSZ * HW)         // 51200
#define NPTS  16384
#define KD    (CC * 9)           // 2304
#define KD3   (3 * KD)           // 6912  (split-tripled conv K)
#define KS3   (3 * CIN)          // 768   (split-tripled stem K)
#define NOUT  85

// ---------------- device scratch ----------------
__device__ __align__(16) __nv_bfloat16 g_xhi[(size_t)NPIX * CIN];
__device__ __align__(16) __nv_bfloat16 g_xlo[(size_t)NPIX * CIN];
__device__ __align__(16) __nv_bfloat16 g_shi[(size_t)NPIX * CC];
__device__ __align__(16) __nv_bfloat16 g_slo[(size_t)NPIX * CC];
__device__ __align__(16) __nv_bfloat16 g_sw[(size_t)CC * KS3];    // stem W' [o][t*256+c]
__device__ __align__(16) __nv_bfloat16 g_cw[(size_t)512 * KD3];   // conv W' [o512][t*2304+q*256+c]
__device__ __align__(16) float g_feat[(size_t)2 * NPTS * CC];     // set0=cls, set1=reg
__device__ __align__(16) float g_predw[96 * 256];
__device__ float g_predb[96];
__device__ int   g_sb[NPTS], g_sy[NPTS], g_sx[NPTS];

__device__ __forceinline__ float silu(float v) {
    return v * (1.0f / (1.0f + __expf(-v)));
}

// ================= warp MMA primitives (sm_80+ path) =================
__device__ __forceinline__ void mma16816(float* d, const uint32_t* a, uint32_t b0, uint32_t b1) {
    asm volatile(
        "mma.sync.aligned.m16n8k16.row.col.f32.bf16.bf16.f32 "
        "{%0,%1,%2,%3}, {%4,%5,%6,%7}, {%8,%9}, {%0,%1,%2,%3};"
        : "+f"(d[0]), "+f"(d[1]), "+f"(d[2]), "+f"(d[3])
        : "r"(a[0]), "r"(a[1]), "r"(a[2]), "r"(a[3]), "r"(b0), "r"(b1));
}
__device__ __forceinline__ void ldsm4(uint32_t* r, uint32_t addr) {
    asm volatile("ldmatrix.sync.aligned.m8n8.x4.shared.b16 {%0,%1,%2,%3}, [%4];"
        : "=r"(r[0]), "=r"(r[1]), "=r"(r[2]), "=r"(r[3]) : "r"(addr));
}
__device__ __forceinline__ uint32_t smem_u32(const void* p) {
    uint32_t a;
    asm("{ .reg .u64 t; cvta.to.shared.u64 t, %1; cvt.u32.u64 %0, t; }" : "=r"(a) : "l"(p));
    return a;
}

// ---- smem tiles: 128 rows x 64 bf16 (128B rows), xor swizzle on 16B chunks ----
// store/load addr = base + row*128 + ((chunk ^ (row&7)) * 16)
#define TILE_BYTES 16384
// dynamic smem: A0 @0, A1 @16384, B0 @32768, B1 @49152 ; total 65536

// Compute one 64-deep K stage: warp (wm,wn), acc[4][4][4].
// A tile [m=128][k=64], B tile [n=128][k=64]; both consumed via NON-trans
// ldmatrix (fragment: thread i holds stored[row=i/4][2*(i%4)..+1]).
__device__ __forceinline__ void compute_stage(uint32_t abase, uint32_t bbase,
                                              int wm, int wn, int lane,
                                              float acc[4][4][4]) {
    const int ar = lane & 15, ac = lane >> 4;                 // A: rows, k-half
    const int bn = (lane & 7) + ((lane >> 4) << 3);           // B: n row within 16
    const int bk = (lane >> 3) & 1;                           // B: k-half chunk
    #pragma unroll
    for (int ks = 0; ks < 4; ks++) {
        uint32_t a[4][4], b[2][4];
        #pragma unroll
        for (int i = 0; i < 4; i++) {
            int row = wm * 64 + i * 16 + ar;
            int ch  = (ks * 2 + ac) ^ (row & 7);
            ldsm4(a[i], abase + row * 128 + ch * 16);
        }
        #pragma unroll
        for (int j = 0; j < 2; j++) {
            int n  = wn * 32 + j * 16 + bn;
            int ch = (ks * 2 + bk) ^ (n & 7);
            ldsm4(b[j], bbase + n * 128 + ch * 16);   // NON-trans (bug fix)
        }
        #pragma unroll
        for (int i = 0; i < 4; i++)
            #pragma unroll
            for (int jj = 0; jj < 4; jj++)
                mma16816(acc[i][jj], a[i], b[jj >> 1][(jj & 1) * 2], b[jj >> 1][(jj & 1) * 2 + 1]);
    }
}

// ================= Kernel 0: decode indices (int64 vs int32 autodetect) ========
__global__ void decode_indices(const int* __restrict__ idx32) {
    int n = blockIdx.x * blockDim.x + threadIdx.x;
    if (n >= NPTS) return;
    bool is64 = true;
    #pragma unroll
    for (int k = 1; k < 24; k += 2) is64 = is64 && (idx32[k] == 0);
    int bi, yi, xi;
    if (is64) { bi = idx32[6 * n]; yi = idx32[6 * n + 2]; xi = idx32[6 * n + 4]; }
    else      { bi = idx32[3 * n]; yi = idx32[3 * n + 1]; xi = idx32[3 * n + 2]; }
    g_sb[n] = bi; g_sy[n] = yi; g_sx[n] = xi;
}

// ================= prep kernels =================
__global__ void prep_x(const float* __restrict__ x) {
    __shared__ float t[32][33];
    int p0 = blockIdx.x * 32, c0 = blockIdx.y * 32, b = blockIdx.z;
    int tx = threadIdx.x, ty = threadIdx.y;
    #pragma unroll
    for (int j = 0; j < 4; j++) {
        int c = c0 + ty + j * 8;
        t[ty + j * 8][tx] = x[((size_t)b * CIN + c) * HW + p0 + tx];
    }
    __syncthreads();
    #pragma unroll
    for (int j = 0; j < 4; j++) {
        int p = p0 + ty + j * 8;
        float v = t[tx][ty + j * 8];
        __nv_bfloat16 hi = __float2bfloat16(v);
        __nv_bfloat16 lo = __float2bfloat16(v - __bfloat162float(hi));
        size_t o = ((size_t)b * HW + p) * CIN + c0 + tx;
        g_xhi[o] = hi; g_xlo[o] = lo;
    }
}

__global__ void prep_sw(const float* __restrict__ w) {
    int idx = blockIdx.x * blockDim.x + threadIdx.x;
    if (idx >= CC * KS3) return;
    int o = idx / KS3, kp = idx % KS3;
    int t = kp / CIN, c = kp % CIN;
    float v = w[o * CIN + c];
    __nv_bfloat16 hi = __float2bfloat16(v);
    g_sw[idx] = (t == 1) ? __float2bfloat16(v - __bfloat162float(hi)) : hi;
}

__global__ void prep_cw(const float* __restrict__ wc, const float* __restrict__ wr) {
    size_t idx = (size_t)blockIdx.x * blockDim.x + threadIdx.x;
    if (idx >= (size_t)512 * KD3) return;
    int o = (int)(idx / KD3), kp = (int)(idx % KD3);
    int t = kp / KD, r = kp % KD, q = r >> 8, c = r & 255;
    int korig = c * 9 + q;
    float v = (o < 256) ? wc[(size_t)o * KD + korig] : wr[(size_t)(o - 256) * KD + korig];
    __nv_bfloat16 hi = __float2bfloat16(v);
    g_cw[idx] = (t == 1) ? __float2bfloat16(v - __bfloat162float(hi)) : hi;
}

__global__ void prep_pw(const float* __restrict__ cw, const float* __restrict__ cb,
                        const float* __restrict__ rw, const float* __restrict__ rb,
                        const float* __restrict__ ow, const float* __restrict__ ob) {
    int idx = blockIdx.x * blockDim.x + threadIdx.x;
    if (idx >= 96 * 256) return;
    int o = idx / 256, k = idx % 256;
    float v = 0.f;
    if (o < 4)       v = rw[o * 256 + k];
    else if (o == 4) v = ow[k];
    else if (o < 85) v = cw[(o - 5) * 256 + k];
    g_predw[idx] = v;
    if (k == 0) {
        float bv = 0.f;
        if (o < 4) bv = rb[o]; else if (o == 4) bv = ob[0]; else if (o < 85) bv = cb[o - 5];
        g_predb[o] = bv;
    }
}

// ================= stem GEMM (mma.sync) =================
// grid (400, 2), 256 thr. M=128 pixels, N=128 outs, K'=768.
__global__ __launch_bounds__(256) void stem_gemm(const float* __restrict__ bias) {
    extern __shared__ char sm[];
    uint32_t smb = smem_u32(sm);
    int tid = threadIdx.x, lane = tid & 31, wid = tid >> 5;
    int wm = wid & 1, wn = wid >> 1;
    int m0 = blockIdx.x * 128;
    int oB = blockIdx.y * 128;

    float acc[4][4][4] = {};
    const int NCH = KS3 / 64;   // 12

    auto load_stage = [&](int buf, int i) {
        int kc = i * 64;
        int t = kc >> 8, c0 = kc & 255;
        const __nv_bfloat16* plane = (t == 2) ? g_xlo : g_xhi;
        char* A = sm + buf * TILE_BYTES;
        char* B = sm + 2 * TILE_BYTES + buf * TILE_BYTES;
        #pragma unroll
        for (int j2 = 0; j2 < 4; j2++) {
            int l = tid + 256 * j2;
            int row = l >> 3, ch = l & 7;
            int sw = (ch ^ (row & 7)) * 16 + row * 128;
            __pipeline_memcpy_async(A + sw, plane + ((size_t)(m0 + row) * CIN + c0 + ch * 8), 16);
            __pipeline_memcpy_async(B + sw, g_sw + ((size_t)(oB + row) * KS3 + kc + ch * 8), 16);
        }
    };

    load_stage(0, 0); __pipeline_commit();
    for (int i = 0; i < NCH; i++) {
        int buf = i & 1;
        if (i + 1 < NCH) {
            load_stage(buf ^ 1, i + 1); __pipeline_commit();
            __pipeline_wait_prior(1);
        } else {
            __pipeline_wait_prior(0);
        }
        __syncthreads();
        compute_stage(smb + buf * TILE_BYTES, smb + 2 * TILE_BYTES + buf * TILE_BYTES,
                      wm, wn, lane, acc);
        __syncthreads();
    }

    int g = lane >> 2, tg = lane & 3;
    #pragma unroll
    for (int i = 0; i < 4; i++) {
        #pragma unroll
        for (int jj = 0; jj < 4; jj++) {
            int col = oB + wn * 32 + jj * 8 + tg * 2;
            float b0 = bias[col], b1 = bias[col + 1];
            int r0 = m0 + wm * 64 + i * 16 + g;
            #pragma unroll
            for (int h = 0; h < 2; h++) {
                int pix = r0 + h * 8;
                float v0 = silu(acc[i][jj][h * 2 + 0] + b0);
                float v1 = silu(acc[i][jj][h * 2 + 1] + b1);
                __nv_bfloat16 h0 = __float2bfloat16(v0);
                __nv_bfloat16 h1 = __float2bfloat16(v1);
                __nv_bfloat162 hp; hp.x = h0; hp.y = h1;
                __nv_bfloat162 lp;
                lp.x = __float2bfloat16(v0 - __bfloat162float(h0));
                lp.y = __float2bfloat16(v1 - __bfloat162float(h1));
                *(__nv_bfloat162*)&g_shi[(size_t)pix * CC + col] = hp;
                *(__nv_bfloat162*)&g_slo[(size_t)pix * CC + col] = lp;
            }
        }
    }
}

// ================= conv GEMM (mma.sync, fused gather) =================
// grid (128, 4), 256 thr. M=128 points, N=128 of 512 outs, K'=6912.
__global__ __launch_bounds__(256) void conv_gemm(const float* __restrict__ bc,
                                                 const float* __restrict__ br) {
    extern __shared__ char sm[];
    __shared__ int ssb[128], ssy[128], ssx[128];
    uint32_t smb = smem_u32(sm);
    int tid = threadIdx.x, lane = tid & 31, wid = tid >> 5;
    int wm = wid & 1, wn = wid >> 1;
    int n0 = blockIdx.x * 128;
    int oB = blockIdx.y * 128;

    if (tid < 128) { ssb[tid] = g_sb[n0 + tid]; ssy[tid] = g_sy[n0 + tid]; ssx[tid] = g_sx[n0 + tid]; }
    __syncthreads();

    float acc[4][4][4] = {};
    const int NCH = KD3 / 64;   // 108

    auto load_stage = [&](int buf, int i) {
        int kc = i * 64;
        int t = kc / KD;
        int r = kc - t * KD;
        int q = r >> 8, c0 = r & 255;
        int kh = q / 3, kw = q - kh * 3;
        const __nv_bfloat16* plane = (t == 2) ? g_slo : g_shi;
        char* A = sm + buf * TILE_BYTES;
        char* B = sm + 2 * TILE_BYTES + buf * TILE_BYTES;
        #pragma unroll
        for (int j2 = 0; j2 < 4; j2++) {
            int l = tid + 256 * j2;
            int row = l >> 3, ch = l & 7;
            int sw = (ch ^ (row & 7)) * 16 + row * 128;
            int y = ssy[row] + kh - 1, xx = ssx[row] + kw - 1;
            bool ok = ((unsigned)y < (unsigned)NYv) && ((unsigned)xx < (unsigned)NXv);
            const __nv_bfloat16* gp = plane +
                ((((size_t)ssb[row] * NYv + (ok ? y : 0)) * NXv + (ok ? xx : 0)) * CC + c0 + ch * 8);
            __pipeline_memcpy_async(A + sw, gp, 16, ok ? 0 : 16);   // zfill when OOB
            __pipeline_memcpy_async(B + sw, g_cw + ((size_t)(oB + row) * KD3 + kc + ch * 8), 16);
        }
    };

    load_stage(0, 0); __pipeline_commit();
    for (int i = 0; i < NCH; i++) {
        int buf = i & 1;
        if (i + 1 < NCH) {
            load_stage(buf ^ 1, i + 1); __pipeline_commit();
            __pipeline_wait_prior(1);
        } else {
            __pipeline_wait_prior(0);
        }
        __syncthreads();
        compute_stage(smb + buf * TILE_BYTES, smb + 2 * TILE_BYTES + buf * TILE_BYTES,
                      wm, wn, lane, acc);
        __syncthreads();
    }

    int g = lane >> 2, tg = lane & 3;
    #pragma unroll
    for (int i = 0; i < 4; i++) {
        #pragma unroll
        for (int jj = 0; jj < 4; jj++) {
            int col = oB + wn * 32 + jj * 8 + tg * 2;
            int set = col >> 8, o = col & 255;
            const float* bp = set ? br : bc;
            float b0 = bp[o], b1 = bp[o + 1];
            int r0 = n0 + wm * 64 + i * 16 + g;
            float2 v;
            v.x = silu(acc[i][jj][0] + b0); v.y = silu(acc[i][jj][1] + b1);
            *(float2*)&g_feat[((size_t)set * NPTS + r0) * CC + o] = v;
            v.x = silu(acc[i][jj][2] + b0); v.y = silu(acc[i][jj][3] + b1);
            *(float2*)&g_feat[((size_t)set * NPTS + r0 + 8) * CC + o] = v;
        }
    }
}

// ================= pred heads =================
__global__ __launch_bounds__(384) void pred_kernel(float* __restrict__ out) {
    __shared__ float sfeat[512];
    int tid = threadIdx.x, wq = tid >> 5, lane = tid & 31;
    int obase = wq * 8;
    int n0 = blockIdx.x * 32;

    float wreg[8][8], bj[8];
    #pragma unroll
    for (int j = 0; j < 8; j++) {
        bj[j] = g_predb[obase + j];
        #pragma unroll
        for (int seg = 0; seg < 8; seg++)
            wreg[j][seg] = g_predw[(obase + j) * 256 + seg * 32 + lane];
    }

    for (int r = 0; r < 32; r++) {
        int n = n0 + r;
        for (int i = tid; i < 512; i += 384) {
            int set = i >> 8, k = i & 255;
            sfeat[i] = g_feat[((size_t)set * NPTS + n) * CC + k];
        }
        __syncthreads();
        float cf[8], rf[8];
        #pragma unroll
        for (int seg = 0; seg < 8; seg++) {
            cf[seg] = sfeat[seg * 32 + lane];
            rf[seg] = sfeat[256 + seg * 32 + lane];
        }
        #pragma unroll
        for (int j = 0; j < 8; j++) {
            bool useReg = (obase + j) < 5;
            float s = 0.f;
            #pragma unroll
            for (int seg = 0; seg < 8; seg++)
                s = fmaf(useReg ? rf[seg] : cf[seg], wreg[j][seg], s);
            #pragma unroll
            for (int off = 16; off > 0; off >>= 1)
                s += __shfl_xor_sync(0xffffffffu, s, off);
            int o = obase + j;
            if (lane == 0 && o < NOUT) out[(size_t)n * NOUT + o] = s + bj[j];
        }
        __syncthreads();
    }
}

// ================= launch =================
extern "C" void kernel_launch(void* const* d_in, const int* in_sizes, int n_in,
                              void* d_out, int out_size) {
    const float* x          = (const float*)d_in[0];
    const int*   indices32  = (const int*)d_in[1];
    const float* stem_w     = (const float*)d_in[2];
    const float* stem_b     = (const float*)d_in[3];
    const float* cls_conv_w = (const float*)d_in[4];
    const float* cls_conv_b = (const float*)d_in[5];
    const float* reg_conv_w = (const float*)d_in[6];
    const float* reg_conv_b = (const float*)d_in[7];
    const float* cls_pred_w = (const float*)d_in[8];
    const float* cls_pred_b = (const float*)d_in[9];
    const float* reg_pred_w = (const float*)d_in[10];
    const float* reg_pred_b = (const float*)d_in[11];
    const float* obj_pred_w = (const float*)d_in[12];
    const float* obj_pred_b = (const float*)d_in[13];
    float* out = (float*)d_out;

    cudaFuncSetAttribute(stem_gemm, cudaFuncAttributeMaxDynamicSharedMemorySize, 4 * TILE_BYTES);
    cudaFuncSetAttribute(conv_gemm, cudaFuncAttributeMaxDynamicSharedMemorySize, 4 * TILE_BYTES);

    decode_indices<<<NPTS / 256, 256>>>(indices32);

    dim3 gx(HW / 32, CIN / 32, BSZ);
    prep_x<<<gx, dim3(32, 8)>>>(x);
    prep_sw<<<(CC * KS3 + 255) / 256, 256>>>(stem_w);
    prep_cw<<<(int)(((size_t)512 * KD3 + 255) / 256), 256>>>(cls_conv_w, reg_conv_w);
    prep_pw<<<(96 * 256 + 255) / 256, 256>>>(cls_pred_w, cls_pred_b,
                                             reg_pred_w, reg_pred_b,
                                             obj_pred_w, obj_pred_b);

    stem_gemm<<<dim3(NPIX / 128, 2), 256, 4 * TILE_BYTES>>>(stem_b);
    conv_gemm<<<dim3(NPTS / 128, 4), 256, 4 * TILE_BYTES>>>(cls_conv_b, reg_conv_b);
    pred_kernel<<<NPTS / 32, 384>>>(out);
}

// round 6
// speedup vs baseline: 3.6604x; 1.2208x over previous
#include <cuda_runtime.h>
#include <cuda_fp16.h>
#include <cuda_pipeline.h>
#include <stdint.h>

// ---------------- problem constants ----------------
#define BSZ   8
#define CIN   256
#define NYv   80
#define NXv   80
#define CC    256
#define HW    (NYv * NXv)        // 6400
#define NPIX  (BSZ * HW)         // 51200
#define NPTS  16384
#define KD    (CC * 9)           // 2304
#define KC2   (2 * KD)           // 4608  (A-split-doubled conv K)
#define KS3   (3 * CIN)          // 768   (split-tripled stem K)
#define NOUT  85

// ---------------- device scratch ----------------
__device__ __align__(16) __half g_xhi[(size_t)NPIX * CIN];
__device__ __align__(16) __half g_xlo[(size_t)NPIX * CIN];
__device__ __align__(16) __half g_shi[(size_t)NPIX * CC];
__device__ __align__(16) __half g_slo[(size_t)NPIX * CC];
__device__ __align__(16) __half g_sw[(size_t)CC * KS3];     // stem W' [o][t*256+c]
__device__ __align__(16) __half g_cw[(size_t)512 * KD];     // conv Whi [o512][q*256+c]
__device__ __align__(16) float g_feat[(size_t)2 * NPTS * CC];   // set0=cls, set1=reg
__device__ __align__(16) float g_predw[96 * 256];
__device__ float g_predb[96];
__device__ int   g_sb[NPTS], g_sy[NPTS], g_sx[NPTS];

__device__ __forceinline__ float silu(float v) {
    return v * (1.0f / (1.0f + __expf(-v)));
}

// ================= warp MMA primitives =================
__device__ __forceinline__ void mma16816(float* d, const uint32_t* a, uint32_t b0, uint32_t b1) {
    asm volatile(
        "mma.sync.aligned.m16n8k16.row.col.f32.f16.f16.f32 "
        "{%0,%1,%2,%3}, {%4,%5,%6,%7}, {%8,%9}, {%0,%1,%2,%3};"
        : "+f"(d[0]), "+f"(d[1]), "+f"(d[2]), "+f"(d[3])
        : "r"(a[0]), "r"(a[1]), "r"(a[2]), "r"(a[3]), "r"(b0), "r"(b1));
}
__device__ __forceinline__ void ldsm4(uint32_t* r, uint32_t addr) {
    asm volatile("ldmatrix.sync.aligned.m8n8.x4.shared.b16 {%0,%1,%2,%3}, [%4];"
        : "=r"(r[0]), "=r"(r[1]), "=r"(r[2]), "=r"(r[3]) : "r"(addr));
}
__device__ __forceinline__ uint32_t smem_u32(const void* p) {
    uint32_t a;
    asm("{ .reg .u64 t; cvta.to.shared.u64 t, %1; cvt.u32.u64 %0, t; }" : "=r"(a) : "l"(p));
    return a;
}

// ---- smem tiles: 128 rows x 64 halves (128B rows), xor swizzle on 16B chunks ----
#define TILE_BYTES 16384
// dynamic smem: A0 @0, A1 @16384, B0 @32768, B1 @49152 ; total 65536

// One 64-deep K stage: warp (wm,wn), acc[4][4][4]. Non-trans ldmatrix both sides.
__device__ __forceinline__ void compute_stage(uint32_t abase, uint32_t bbase,
                                              int wm, int wn, int lane,
                                              float acc[4][4][4]) {
    const int ar = lane & 15, ac = lane >> 4;
    const int bn = (lane & 7) + ((lane >> 4) << 3);
    const int bk = (lane >> 3) & 1;
    #pragma unroll
    for (int ks = 0; ks < 4; ks++) {
        uint32_t a[4][4], b[2][4];
        #pragma unroll
        for (int i = 0; i < 4; i++) {
            int row = wm * 64 + i * 16 + ar;
            int ch  = (ks * 2 + ac) ^ (row & 7);
            ldsm4(a[i], abase + row * 128 + ch * 16);
        }
        #pragma unroll
        for (int j = 0; j < 2; j++) {
            int n  = wn * 32 + j * 16 + bn;
            int ch = (ks * 2 + bk) ^ (n & 7);
            ldsm4(b[j], bbase + n * 128 + ch * 16);
        }
        #pragma unroll
        for (int i = 0; i < 4; i++)
            #pragma unroll
            for (int jj = 0; jj < 4; jj++)
                mma16816(acc[i][jj], a[i], b[jj >> 1][(jj & 1) * 2], b[jj >> 1][(jj & 1) * 2 + 1]);
    }
}

// ================= Kernel 0: decode indices (int64/int32 autodetect) ========
__global__ void decode_indices(const int* __restrict__ idx32) {
    int n = blockIdx.x * blockDim.x + threadIdx.x;
    if (n >= NPTS) return;
    bool is64 = true;
    #pragma unroll
    for (int k = 1; k < 24; k += 2) is64 = is64 && (idx32[k] == 0);
    int bi, yi, xi;
    if (is64) { bi = idx32[6 * n]; yi = idx32[6 * n + 2]; xi = idx32[6 * n + 4]; }
    else      { bi = idx32[3 * n]; yi = idx32[3 * n + 1]; xi = idx32[3 * n + 2]; }
    g_sb[n] = bi; g_sy[n] = yi; g_sx[n] = xi;
}

// ================= prep kernels =================
__global__ void prep_x(const float* __restrict__ x) {
    __shared__ float t[32][33];
    int p0 = blockIdx.x * 32, c0 = blockIdx.y * 32, b = blockIdx.z;
    int tx = threadIdx.x, ty = threadIdx.y;
    #pragma unroll
    for (int j = 0; j < 4; j++) {
        int c = c0 + ty + j * 8;
        t[ty + j * 8][tx] = x[((size_t)b * CIN + c) * HW + p0 + tx];
    }
    __syncthreads();
    #pragma unroll
    for (int j = 0; j < 4; j++) {
        int p = p0 + ty + j * 8;
        float v = t[tx][ty + j * 8];
        __half hi = __float2half_rn(v);
        __half lo = __float2half_rn(v - __half2float(hi));
        size_t o = ((size_t)b * HW + p) * CIN + c0 + tx;
        g_xhi[o] = hi; g_xlo[o] = lo;
    }
}

// stem W' fp16 3-term: t0 hi, t1 lo, t2 hi (pairs with A planes xhi,xhi,xlo)
__global__ void prep_sw(const float* __restrict__ w) {
    int idx = blockIdx.x * blockDim.x + threadIdx.x;
    if (idx >= CC * KS3) return;
    int o = idx / KS3, kp = idx % KS3;
    int t = kp / CIN, c = kp % CIN;
    float v = w[o * CIN + c];
    __half hi = __float2half_rn(v);
    g_cw[0] = g_cw[0];  // no-op
    g_sw[idx] = (t == 1) ? __float2half_rn(v - __half2float(hi)) : hi;
}

// conv Whi fp16 single plane: [o512][q*256+c], korig = c*9+q
__global__ void prep_cw(const float* __restrict__ wc, const float* __restrict__ wr) {
    size_t idx = (size_t)blockIdx.x * blockDim.x + threadIdx.x;
    if (idx >= (size_t)512 * KD) return;
    int o = (int)(idx / KD), r = (int)(idx % KD);
    int q = r >> 8, c = r & 255;
    int korig = c * 9 + q;
    float v = (o < 256) ? wc[(size_t)o * KD + korig] : wr[(size_t)(o - 256) * KD + korig];
    g_cw[idx] = __float2half_rn(v);
}

__global__ void prep_pw(const float* __restrict__ cw, const float* __restrict__ cb,
                        const float* __restrict__ rw, const float* __restrict__ rb,
                        const float* __restrict__ ow, const float* __restrict__ ob) {
    int idx = blockIdx.x * blockDim.x + threadIdx.x;
    if (idx >= 96 * 256) return;
    int o = idx / 256, k = idx % 256;
    float v = 0.f;
    if (o < 4)       v = rw[o * 256 + k];
    else if (o == 4) v = ow[k];
    else if (o < 85) v = cw[(o - 5) * 256 + k];
    g_predw[idx] = v;
    if (k == 0) {
        float bv = 0.f;
        if (o < 4) bv = rb[o]; else if (o == 4) bv = ob[0]; else if (o < 85) bv = cb[o - 5];
        g_predb[o] = bv;
    }
}

// ================= stem GEMM (mma.sync fp16 3-term) =================
// grid (400, 2), 256 thr. M=128 pixels, N=128 outs, K'=768.
__global__ __launch_bounds__(256) void stem_gemm(const float* __restrict__ bias) {
    extern __shared__ char sm[];
    uint32_t smb = smem_u32(sm);
    int tid = threadIdx.x, lane = tid & 31, wid = tid >> 5;
    int wm = wid & 1, wn = wid >> 1;
    int m0 = blockIdx.x * 128;
    int oB = blockIdx.y * 128;

    float acc[4][4][4] = {};
    const int NCH = KS3 / 64;   // 12

    auto load_stage = [&](int buf, int i) {
        int kc = i * 64;
        int t = kc >> 8, c0 = kc & 255;
        const __half* plane = (t == 2) ? g_xlo : g_xhi;
        char* A = sm + buf * TILE_BYTES;
        char* B = sm + 2 * TILE_BYTES + buf * TILE_BYTES;
        #pragma unroll
        for (int j2 = 0; j2 < 4; j2++) {
            int l = tid + 256 * j2;
            int row = l >> 3, ch = l & 7;
            int sw = (ch ^ (row & 7)) * 16 + row * 128;
            __pipeline_memcpy_async(A + sw, plane + ((size_t)(m0 + row) * CIN + c0 + ch * 8), 16);
            __pipeline_memcpy_async(B + sw, g_sw + ((size_t)(oB + row) * KS3 + kc + ch * 8), 16);
        }
    };

    load_stage(0, 0); __pipeline_commit();
    for (int i = 0; i < NCH; i++) {
        int buf = i & 1;
        if (i + 1 < NCH) {
            load_stage(buf ^ 1, i + 1); __pipeline_commit();
            __pipeline_wait_prior(1);
        } else {
            __pipeline_wait_prior(0);
        }
        __syncthreads();
        compute_stage(smb + buf * TILE_BYTES, smb + 2 * TILE_BYTES + buf * TILE_BYTES,
                      wm, wn, lane, acc);
        __syncthreads();
    }

    int g = lane >> 2, tg = lane & 3;
    #pragma unroll
    for (int i = 0; i < 4; i++) {
        #pragma unroll
        for (int jj = 0; jj < 4; jj++) {
            int col = oB + wn * 32 + jj * 8 + tg * 2;
            float b0 = bias[col], b1 = bias[col + 1];
            int r0 = m0 + wm * 64 + i * 16 + g;
            #pragma unroll
            for (int h = 0; h < 2; h++) {
                int pix = r0 + h * 8;
                float v0 = silu(acc[i][jj][h * 2 + 0] + b0);
                float v1 = silu(acc[i][jj][h * 2 + 1] + b1);
                __half h0 = __float2half_rn(v0);
                __half h1 = __float2half_rn(v1);
                __half2 hp; hp.x = h0; hp.y = h1;
                __half2 lp;
                lp.x = __float2half_rn(v0 - __half2float(h0));
                lp.y = __float2half_rn(v1 - __half2float(h1));
                *(__half2*)&g_shi[(size_t)pix * CC + col] = hp;
                *(__half2*)&g_slo[(size_t)pix * CC + col] = lp;
            }
        }
    }
}

// ================= conv GEMM (mma.sync fp16 2-term, fused gather) ==========
// grid (128, 4), 256 thr. M=128 points, N=128 of 512 outs, K'=4608.
// A' = [Shi | Slo]; B reads the SAME Whi plane for both halves.
__global__ __launch_bounds__(256) void conv_gemm(const float* __restrict__ bc,
                                                 const float* __restrict__ br) {
    extern __shared__ char sm[];
    __shared__ int ssb[128], ssy[128], ssx[128];
    uint32_t smb = smem_u32(sm);
    int tid = threadIdx.x, lane = tid & 31, wid = tid >> 5;
    int wm = wid & 1, wn = wid >> 1;
    int n0 = blockIdx.x * 128;
    int oB = blockIdx.y * 128;

    if (tid < 128) { ssb[tid] = g_sb[n0 + tid]; ssy[tid] = g_sy[n0 + tid]; ssx[tid] = g_sx[n0 + tid]; }
    __syncthreads();

    float acc[4][4][4] = {};
    const int NCH = KC2 / 64;   // 72

    auto load_stage = [&](int buf, int i) {
        int kc = i * 64;
        int t = kc / KD;
        int r = kc - t * KD;
        int q = r >> 8, c0 = r & 255;
        int kh = q / 3, kw = q - kh * 3;
        const __half* plane = (t == 1) ? g_slo : g_shi;
        char* A = sm + buf * TILE_BYTES;
        char* B = sm + 2 * TILE_BYTES + buf * TILE_BYTES;
        #pragma unroll
        for (int j2 = 0; j2 < 4; j2++) {
            int l = tid + 256 * j2;
            int row = l >> 3, ch = l & 7;
            int sw = (ch ^ (row & 7)) * 16 + row * 128;
            int y = ssy[row] + kh - 1, xx = ssx[row] + kw - 1;
            bool ok = ((unsigned)y < (unsigned)NYv) && ((unsigned)xx < (unsigned)NXv);
            const __half* gp = plane +
                ((((size_t)ssb[row] * NYv + (ok ? y : 0)) * NXv + (ok ? xx : 0)) * CC + c0 + ch * 8);
            __pipeline_memcpy_async(A + sw, gp, 16, ok ? 0 : 16);   // zfill when OOB
            __pipeline_memcpy_async(B + sw, g_cw + ((size_t)(oB + row) * KD + r + ch * 8), 16);
        }
    };

    load_stage(0, 0); __pipeline_commit();
    for (int i = 0; i < NCH; i++) {
        int buf = i & 1;
        if (i + 1 < NCH) {
            load_stage(buf ^ 1, i + 1); __pipeline_commit();
            __pipeline_wait_prior(1);
        } else {
            __pipeline_wait_prior(0);
        }
        __syncthreads();
        compute_stage(smb + buf * TILE_BYTES, smb + 2 * TILE_BYTES + buf * TILE_BYTES,
                      wm, wn, lane, acc);
        __syncthreads();
    }

    int g = lane >> 2, tg = lane & 3;
    #pragma unroll
    for (int i = 0; i < 4; i++) {
        #pragma unroll
        for (int jj = 0; jj < 4; jj++) {
            int col = oB + wn * 32 + jj * 8 + tg * 2;
            int set = col >> 8, o = col & 255;
            const float* bp = set ? br : bc;
            float b0 = bp[o], b1 = bp[o + 1];
            int r0 = n0 + wm * 64 + i * 16 + g;
            float2 v;
            v.x = silu(acc[i][jj][0] + b0); v.y = silu(acc[i][jj][1] + b1);
            *(float2*)&g_feat[((size_t)set * NPTS + r0) * CC + o] = v;
            v.x = silu(acc[i][jj][2] + b0); v.y = silu(acc[i][jj][3] + b1);
            *(float2*)&g_feat[((size_t)set * NPTS + r0 + 8) * CC + o] = v;
        }
    }
}

// ================= pred heads =================
__global__ __launch_bounds__(384) void pred_kernel(float* __restrict__ out) {
    __shared__ float sfeat[512];
    int tid = threadIdx.x, wq = tid >> 5, lane = tid & 31;
    int obase = wq * 8;
    int n0 = blockIdx.x * 32;

    float wreg[8][8], bj[8];
    #pragma unroll
    for (int j = 0; j < 8; j++) {
        bj[j] = g_predb[obase + j];
        #pragma unroll
        for (int seg = 0; seg < 8; seg++)
            wreg[j][seg] = g_predw[(obase + j) * 256 + seg * 32 + lane];
    }

    for (int r = 0; r < 32; r++) {
        int n = n0 + r;
        for (int i = tid; i < 512; i += 384) {
            int set = i >> 8, k = i & 255;
            sfeat[i] = g_feat[((size_t)set * NPTS + n) * CC + k];
        }
        __syncthreads();
        float cf[8], rf[8];
        #pragma unroll
        for (int seg = 0; seg < 8; seg++) {
            cf[seg] = sfeat[seg * 32 + lane];
            rf[seg] = sfeat[256 + seg * 32 + lane];
        }
        #pragma unroll
        for (int j = 0; j < 8; j++) {
            bool useReg = (obase + j) < 5;
            float s = 0.f;
            #pragma unroll
            for (int seg = 0; seg < 8; seg++)
                s = fmaf(useReg ? rf[seg] : cf[seg], wreg[j][seg], s);
            #pragma unroll
            for (int off = 16; off > 0; off >>= 1)
                s += __shfl_xor_sync(0xffffffffu, s, off);
            int o = obase + j;
            if (lane == 0 && o < NOUT) out[(size_t)n * NOUT + o] = s + bj[j];
        }
        __syncthreads();
    }
}

// ================= launch =================
extern "C" void kernel_launch(void* const* d_in, const int* in_sizes, int n_in,
                              void* d_out, int out_size) {
    const float* x          = (const float*)d_in[0];
    const int*   indices32  = (const int*)d_in[1];
    const float* stem_w     = (const float*)d_in[2];
    const float* stem_b     = (const float*)d_in[3];
    const float* cls_conv_w = (const float*)d_in[4];
    const float* cls_conv_b = (const float*)d_in[5];
    const float* reg_conv_w = (const float*)d_in[6];
    const float* reg_conv_b = (const float*)d_in[7];
    const float* cls_pred_w = (const float*)d_in[8];
    const float* cls_pred_b = (const float*)d_in[9];
    const float* reg_pred_w = (const float*)d_in[10];
    const float* reg_pred_b = (const float*)d_in[11];
    const float* obj_pred_w = (const float*)d_in[12];
    const float* obj_pred_b = (const float*)d_in[13];
    float* out = (float*)d_out;

    cudaFuncSetAttribute(stem_gemm, cudaFuncAttributeMaxDynamicSharedMemorySize, 4 * TILE_BYTES);
    cudaFuncSetAttribute(conv_gemm, cudaFuncAttributeMaxDynamicSharedMemorySize, 4 * TILE_BYTES);

    decode_indices<<<NPTS / 256, 256>>>(indices32);

    dim3 gx(HW / 32, CIN / 32, BSZ);
    prep_x<<<gx, dim3(32, 8)>>>(x);
    prep_sw<<<(CC * KS3 + 255) / 256, 256>>>(stem_w);
    prep_cw<<<(int)(((size_t)512 * KD + 255) / 256), 256>>>(cls_conv_w, reg_conv_w);
    prep_pw<<<(96 * 256 + 255) / 256, 256>>>(cls_pred_w, cls_pred_b,
                                             reg_pred_w, reg_pred_b,
                                             obj_pred_w, obj_pred_b);

    stem_gemm<<<dim3(NPIX / 128, 2), 256, 4 * TILE_BYTES>>>(stem_b);
    conv_gemm<<<dim3(NPTS / 128, 4), 256, 4 * TILE_BYTES>>>(cls_conv_b, reg_conv_b);
    pred_kernel<<<NPTS / 32, 384>>>(out);
}

// round 7
// speedup vs baseline: 3.7611x; 1.0275x over previous
#include <cuda_runtime.h>
#include <cuda_fp16.h>
#include <cuda_pipeline.h>
#include <stdint.h>

// ---------------- problem constants ----------------
#define BSZ   8
#define CIN   256
#define NYv   80
#define NXv   80
#define CC    256
#define HW    (NYv * NXv)        // 6400
#define NPIX  (BSZ * HW)         // 51200
#define NPTS  16384
#define KD    (CC * 9)           // 2304
#define KC2   (2 * KD)           // 4608  (A-split-doubled conv K)
#define KS3   (3 * CIN)          // 768   (split-tripled stem K)
#define NOUT  85

// ---------------- device scratch ----------------
__device__ __align__(16) __half g_xhi[(size_t)NPIX * CIN];
__device__ __align__(16) __half g_xlo[(size_t)NPIX * CIN];
__device__ __align__(16) __half g_shi[(size_t)NPIX * CC];
__device__ __align__(16) __half g_slo[(size_t)NPIX * CC];
__device__ __align__(16) __half g_sw[(size_t)CC * KS3];     // stem W' [o][t*256+c]
__device__ __align__(16) __half g_cw[(size_t)512 * KD];     // conv Whi [o512][q*256+c]
__device__ __align__(16) float g_feat[(size_t)2 * NPTS * CC];   // set0=cls, set1=reg
__device__ __align__(16) float g_predw[96 * 256];
__device__ float g_predb[96];
__device__ int   g_sb[NPTS], g_sy[NPTS], g_sx[NPTS];

__device__ __forceinline__ float silu(float v) {
    return v * (1.0f / (1.0f + __expf(-v)));
}

// ================= warp MMA primitives =================
__device__ __forceinline__ void mma16816(float* d, const uint32_t* a, uint32_t b0, uint32_t b1) {
    asm volatile(
        "mma.sync.aligned.m16n8k16.row.col.f32.f16.f16.f32 "
        "{%0,%1,%2,%3}, {%4,%5,%6,%7}, {%8,%9}, {%0,%1,%2,%3};"
        : "+f"(d[0]), "+f"(d[1]), "+f"(d[2]), "+f"(d[3])
        : "r"(a[0]), "r"(a[1]), "r"(a[2]), "r"(a[3]), "r"(b0), "r"(b1));
}
__device__ __forceinline__ void ldsm4(uint32_t* r, uint32_t addr) {
    asm volatile("ldmatrix.sync.aligned.m8n8.x4.shared.b16 {%0,%1,%2,%3}, [%4];"
        : "=r"(r[0]), "=r"(r[1]), "=r"(r[2]), "=r"(r[3]) : "r"(addr));
}
__device__ __forceinline__ uint32_t smem_u32(const void* p) {
    uint32_t a;
    asm("{ .reg .u64 t; cvta.to.shared.u64 t, %1; cvt.u32.u64 %0, t; }" : "=r"(a) : "l"(p));
    return a;
}

// ---- smem rows: 64 halves = 128B, xor swizzle on 16B chunks ----
// addr = base + row*128 + ((chunk ^ (row&7)) * 16)
#define A_TILE 16384             // 128 rows
#define B_TILE_CONV 32768        // 256 rows
// conv smem: A0/A1/A2 @ 0/16K/32K, B0/B1/B2 @ 48K/80K/112K -> 144KB
#define CV_SMEM (3 * A_TILE + 3 * B_TILE_CONV)
// stem smem: A0/A1 @0/16K, B0/B1 @32K/48K -> 64KB
#define ST_SMEM (4 * A_TILE)

// One 64-deep K stage for one warp (tile 64x32), acc[4][4][4].
__device__ __forceinline__ void compute_stage(uint32_t abase, uint32_t bbase,
                                              int wm, int wn, int lane,
                                              float acc[4][4][4]) {
    const int ar = lane & 15, ac = lane >> 4;
    const int bn = (lane & 7) + ((lane >> 4) << 3);
    const int bk = (lane >> 3) & 1;
    #pragma unroll
    for (int ks = 0; ks < 4; ks++) {
        uint32_t a[4][4], b[2][4];
        #pragma unroll
        for (int i = 0; i < 4; i++) {
            int row = wm * 64 + i * 16 + ar;
            int ch  = (ks * 2 + ac) ^ (row & 7);
            ldsm4(a[i], abase + row * 128 + ch * 16);
        }
        #pragma unroll
        for (int j = 0; j < 2; j++) {
            int n  = wn * 32 + j * 16 + bn;
            int ch = (ks * 2 + bk) ^ (n & 7);
            ldsm4(b[j], bbase + n * 128 + ch * 16);
        }
        #pragma unroll
        for (int i = 0; i < 4; i++)
            #pragma unroll
            for (int jj = 0; jj < 4; jj++)
                mma16816(acc[i][jj], a[i], b[jj >> 1][(jj & 1) * 2], b[jj >> 1][(jj & 1) * 2 + 1]);
    }
}

// ================= Kernel 0: decode indices (int64/int32 autodetect) ========
__global__ void decode_indices(const int* __restrict__ idx32) {
    int n = blockIdx.x * blockDim.x + threadIdx.x;
    if (n >= NPTS) return;
    bool is64 = true;
    #pragma unroll
    for (int k = 1; k < 24; k += 2) is64 = is64 && (idx32[k] == 0);
    int bi, yi, xi;
    if (is64) { bi = idx32[6 * n]; yi = idx32[6 * n + 2]; xi = idx32[6 * n + 4]; }
    else      { bi = idx32[3 * n]; yi = idx32[3 * n + 1]; xi = idx32[3 * n + 2]; }
    g_sb[n] = bi; g_sy[n] = yi; g_sx[n] = xi;
}

// ================= prep kernels =================
__global__ void prep_x(const float* __restrict__ x) {
    __shared__ float t[32][33];
    int p0 = blockIdx.x * 32, c0 = blockIdx.y * 32, b = blockIdx.z;
    int tx = threadIdx.x, ty = threadIdx.y;
    #pragma unroll
    for (int j = 0; j < 4; j++) {
        int c = c0 + ty + j * 8;
        t[ty + j * 8][tx] = x[((size_t)b * CIN + c) * HW + p0 + tx];
    }
    __syncthreads();
    #pragma unroll
    for (int j = 0; j < 4; j++) {
        int p = p0 + ty + j * 8;
        float v = t[tx][ty + j * 8];
        __half hi = __float2half_rn(v);
        __half lo = __float2half_rn(v - __half2float(hi));
        size_t o = ((size_t)b * HW + p) * CIN + c0 + tx;
        g_xhi[o] = hi; g_xlo[o] = lo;
    }
}

// stem W' fp16 3-term: t0 hi, t1 lo, t2 hi (pairs with A planes xhi,xhi,xlo)
__global__ void prep_sw(const float* __restrict__ w) {
    int idx = blockIdx.x * blockDim.x + threadIdx.x;
    if (idx >= CC * KS3) return;
    int o = idx / KS3, kp = idx % KS3;
    int t = kp / CIN, c = kp % CIN;
    float v = w[o * CIN + c];
    __half hi = __float2half_rn(v);
    g_sw[idx] = (t == 1) ? __float2half_rn(v - __half2float(hi)) : hi;
}

// conv Whi fp16 single plane: [o512][q*256+c], korig = c*9+q
__global__ void prep_cw(const float* __restrict__ wc, const float* __restrict__ wr) {
    size_t idx = (size_t)blockIdx.x * blockDim.x + threadIdx.x;
    if (idx >= (size_t)512 * KD) return;
    int o = (int)(idx / KD), r = (int)(idx % KD);
    int q = r >> 8, c = r & 255;
    int korig = c * 9 + q;
    float v = (o < 256) ? wc[(size_t)o * KD + korig] : wr[(size_t)(o - 256) * KD + korig];
    g_cw[idx] = __float2half_rn(v);
}

__global__ void prep_pw(const float* __restrict__ cw, const float* __restrict__ cb,
                        const float* __restrict__ rw, const float* __restrict__ rb,
                        const float* __restrict__ ow, const float* __restrict__ ob) {
    int idx = blockIdx.x * blockDim.x + threadIdx.x;
    if (idx >= 96 * 256) return;
    int o = idx / 256, k = idx % 256;
    float v = 0.f;
    if (o < 4)       v = rw[o * 256 + k];
    else if (o == 4) v = ow[k];
    else if (o < 85) v = cw[(o - 5) * 256 + k];
    g_predw[idx] = v;
    if (k == 0) {
        float bv = 0.f;
        if (o < 4) bv = rb[o]; else if (o == 4) bv = ob[0]; else if (o < 85) bv = cb[o - 5];
        g_predb[o] = bv;
    }
}

// ================= stem GEMM (fp16 3-term, 2-stage) =================
// grid (400, 2), 256 thr. M=128 pixels, N=128 outs, K'=768.
__global__ __launch_bounds__(256) void stem_gemm(const float* __restrict__ bias) {
    extern __shared__ char sm[];
    uint32_t smb = smem_u32(sm);
    int tid = threadIdx.x, lane = tid & 31, wid = tid >> 5;
    int wm = wid & 1, wn = wid >> 1;
    int m0 = blockIdx.x * 128;
    int oB = blockIdx.y * 128;

    float acc[4][4][4] = {};
    const int NCH = KS3 / 64;   // 12

    auto load_stage = [&](int buf, int i) {
        int kc = i * 64;
        int t = kc >> 8, c0 = kc & 255;
        const __half* plane = (t == 2) ? g_xlo : g_xhi;
        char* A = sm + buf * A_TILE;
        char* B = sm + 2 * A_TILE + buf * A_TILE;
        #pragma unroll
        for (int j2 = 0; j2 < 4; j2++) {
            int l = tid + 256 * j2;
            int row = l >> 3, ch = l & 7;
            int sw = (ch ^ (row & 7)) * 16 + row * 128;
            __pipeline_memcpy_async(A + sw, plane + ((size_t)(m0 + row) * CIN + c0 + ch * 8), 16);
            __pipeline_memcpy_async(B + sw, g_sw + ((size_t)(oB + row) * KS3 + kc + ch * 8), 16);
        }
    };

    load_stage(0, 0); __pipeline_commit();
    for (int i = 0; i < NCH; i++) {
        int buf = i & 1;
        if (i + 1 < NCH) {
            load_stage(buf ^ 1, i + 1); __pipeline_commit();
            __pipeline_wait_prior(1);
        } else {
            __pipeline_wait_prior(0);
        }
        __syncthreads();
        compute_stage(smb + buf * A_TILE, smb + 2 * A_TILE + buf * A_TILE,
                      wm, wn, lane, acc);
        __syncthreads();
    }

    int g = lane >> 2, tg = lane & 3;
    #pragma unroll
    for (int i = 0; i < 4; i++) {
        #pragma unroll
        for (int jj = 0; jj < 4; jj++) {
            int col = oB + wn * 32 + jj * 8 + tg * 2;
            float b0 = bias[col], b1 = bias[col + 1];
            int r0 = m0 + wm * 64 + i * 16 + g;
            #pragma unroll
            for (int h = 0; h < 2; h++) {
                int pix = r0 + h * 8;
                float v0 = silu(acc[i][jj][h * 2 + 0] + b0);
                float v1 = silu(acc[i][jj][h * 2 + 1] + b1);
                __half h0 = __float2half_rn(v0);
                __half h1 = __float2half_rn(v1);
                __half2 hp; hp.x = h0; hp.y = h1;
                __half2 lp;
                lp.x = __float2half_rn(v0 - __half2float(h0));
                lp.y = __float2half_rn(v1 - __half2float(h1));
                *(__half2*)&g_shi[(size_t)pix * CC + col] = hp;
                *(__half2*)&g_slo[(size_t)pix * CC + col] = lp;
            }
        }
    }
}

// ================= conv GEMM (fp16 2-term, fused gather, 3-stage) ==========
// grid (128, 2), 512 thr (16 warps: wm 2 x wn 8). M=128 pts, N=256 outs, K'=4608.
__global__ __launch_bounds__(512) void conv_gemm(const float* __restrict__ bc,
                                                 const float* __restrict__ br) {
    extern __shared__ char sm[];
    __shared__ int ssb[128], ssy[128], ssx[128];
    uint32_t smb = smem_u32(sm);
    int tid = threadIdx.x, lane = tid & 31, wid = tid >> 5;
    int wm = wid & 1, wn = wid >> 1;       // wn 0..7
    int n0 = blockIdx.x * 128;
    int oB = blockIdx.y * 256;

    if (tid < 128) { ssb[tid] = g_sb[n0 + tid]; ssy[tid] = g_sy[n0 + tid]; ssx[tid] = g_sx[n0 + tid]; }
    __syncthreads();

    float acc[4][4][4] = {};
    const int NCH = KC2 / 64;   // 72

    auto load_stage = [&](int buf, int i) {
        int kc = i * 64;
        int t = kc / KD;
        int r = kc - t * KD;
        int q = r >> 8, c0 = r & 255;
        int kh = q / 3, kw = q - kh * 3;
        const __half* plane = (t == 1) ? g_slo : g_shi;
        char* A = sm + buf * A_TILE;
        char* B = sm + 3 * A_TILE + buf * B_TILE_CONV;
        // A: 128 rows -> 1024 chunks / 512 thr = 2 each
        #pragma unroll
        for (int j2 = 0; j2 < 2; j2++) {
            int l = tid + 512 * j2;
            int row = l >> 3, ch = l & 7;
            int sw = (ch ^ (row & 7)) * 16 + row * 128;
            int y = ssy[row] + kh - 1, xx = ssx[row] + kw - 1;
            bool ok = ((unsigned)y < (unsigned)NYv) && ((unsigned)xx < (unsigned)NXv);
            const __half* gp = plane +
                ((((size_t)ssb[row] * NYv + (ok ? y : 0)) * NXv + (ok ? xx : 0)) * CC + c0 + ch * 8);
            __pipeline_memcpy_async(A + sw, gp, 16, ok ? 0 : 16);   // zfill when OOB
        }
        // B: 256 rows -> 2048 chunks / 512 thr = 4 each
        #pragma unroll
        for (int j2 = 0; j2 < 4; j2++) {
            int l = tid + 512 * j2;
            int row = l >> 3, ch = l & 7;
            int sw = (ch ^ (row & 7)) * 16 + row * 128;
            __pipeline_memcpy_async(B + sw, g_cw + ((size_t)(oB + row) * KD + r + ch * 8), 16);
        }
    };

    load_stage(0, 0); __pipeline_commit();
    load_stage(1, 1); __pipeline_commit();
    for (int i = 0; i < NCH; i++) {
        int buf = i % 3;
        if (i + 2 < NCH) {
            load_stage((i + 2) % 3, i + 2); __pipeline_commit();
            __pipeline_wait_prior(2);
        } else if (i + 1 < NCH) {
            __pipeline_wait_prior(1);
        } else {
            __pipeline_wait_prior(0);
        }
        __syncthreads();
        compute_stage(smb + buf * A_TILE, smb + 3 * A_TILE + buf * B_TILE_CONV,
                      wm, wn, lane, acc);
        __syncthreads();
    }

    int g = lane >> 2, tg = lane & 3;
    #pragma unroll
    for (int i = 0; i < 4; i++) {
        #pragma unroll
        for (int jj = 0; jj < 4; jj++) {
            int col = oB + wn * 32 + jj * 8 + tg * 2;
            int set = col >> 8, o = col & 255;
            const float* bp = set ? br : bc;
            float b0 = bp[o], b1 = bp[o + 1];
            int r0 = n0 + wm * 64 + i * 16 + g;
            float2 v;
            v.x = silu(acc[i][jj][0] + b0); v.y = silu(acc[i][jj][1] + b1);
            *(float2*)&g_feat[((size_t)set * NPTS + r0) * CC + o] = v;
            v.x = silu(acc[i][jj][2] + b0); v.y = silu(acc[i][jj][3] + b1);
            *(float2*)&g_feat[((size_t)set * NPTS + r0 + 8) * CC + o] = v;
        }
    }
}

// ================= pred heads =================
__global__ __launch_bounds__(384) void pred_kernel(float* __restrict__ out) {
    __shared__ float sfeat[512];
    int tid = threadIdx.x, wq = tid >> 5, lane = tid & 31;
    int obase = wq * 8;
    int n0 = blockIdx.x * 32;

    float wreg[8][8], bj[8];
    #pragma unroll
    for (int j = 0; j < 8; j++) {
        bj[j] = g_predb[obase + j];
        #pragma unroll
        for (int seg = 0; seg < 8; seg++)
            wreg[j][seg] = g_predw[(obase + j) * 256 + seg * 32 + lane];
    }

    for (int r = 0; r < 32; r++) {
        int n = n0 + r;
        for (int i = tid; i < 512; i += 384) {
            int set = i >> 8, k = i & 255;
            sfeat[i] = g_feat[((size_t)set * NPTS + n) * CC + k];
        }
        __syncthreads();
        float cf[8], rf[8];
        #pragma unroll
        for (int seg = 0; seg < 8; seg++) {
            cf[seg] = sfeat[seg * 32 + lane];
            rf[seg] = sfeat[256 + seg * 32 + lane];
        }
        #pragma unroll
        for (int j = 0; j < 8; j++) {
            bool useReg = (obase + j) < 5;
            float s = 0.f;
            #pragma unroll
            for (int seg = 0; seg < 8; seg++)
                s = fmaf(useReg ? rf[seg] : cf[seg], wreg[j][seg], s);
            #pragma unroll
            for (int off = 16; off > 0; off >>= 1)
                s += __shfl_xor_sync(0xffffffffu, s, off);
            int o = obase + j;
            if (lane == 0 && o < NOUT) out[(size_t)n * NOUT + o] = s + bj[j];
        }
        __syncthreads();
    }
}

// ================= launch =================
extern "C" void kernel_launch(void* const* d_in, const int* in_sizes, int n_in,
                              void* d_out, int out_size) {
    const float* x          = (const float*)d_in[0];
    const int*   indices32  = (const int*)d_in[1];
    const float* stem_w     = (const float*)d_in[2];
    const float* stem_b     = (const float*)d_in[3];
    const float* cls_conv_w = (const float*)d_in[4];
    const float* cls_conv_b = (const float*)d_in[5];
    const float* reg_conv_w = (const float*)d_in[6];
    const float* reg_conv_b = (const float*)d_in[7];
    const float* cls_pred_w = (const float*)d_in[8];
    const float* cls_pred_b = (const float*)d_in[9];
    const float* reg_pred_w = (const float*)d_in[10];
    const float* reg_pred_b = (const float*)d_in[11];
    const float* obj_pred_w = (const float*)d_in[12];
    const float* obj_pred_b = (const float*)d_in[13];
    float* out = (float*)d_out;

    cudaFuncSetAttribute(stem_gemm, cudaFuncAttributeMaxDynamicSharedMemorySize, ST_SMEM);
    cudaFuncSetAttribute(conv_gemm, cudaFuncAttributeMaxDynamicSharedMemorySize, CV_SMEM);

    decode_indices<<<NPTS / 256, 256>>>(indices32);

    dim3 gx(HW / 32, CIN / 32, BSZ);
    prep_x<<<gx, dim3(32, 8)>>>(x);
    prep_sw<<<(CC * KS3 + 255) / 256, 256>>>(stem_w);
    prep_cw<<<(int)(((size_t)512 * KD + 255) / 256), 256>>>(cls_conv_w, reg_conv_w);
    prep_pw<<<(96 * 256 + 255) / 256, 256>>>(cls_pred_w, cls_pred_b,
                                             reg_pred_w, reg_pred_b,
                                             obj_pred_w, obj_pred_b);

    stem_gemm<<<dim3(NPIX / 128, 2), 256, ST_SMEM>>>(stem_b);
    conv_gemm<<<dim3(NPTS / 128, 2), 512, CV_SMEM>>>(cls_conv_b, reg_conv_b);
    pred_kernel<<<NPTS / 32, 384>>>(out);
}

// round 8
// speedup vs baseline: 5.3385x; 1.4194x over previous
#include <cuda_runtime.h>
#include <cuda_fp16.h>
#include <cuda_pipeline.h>
#include <stdint.h>

// ---------------- problem constants ----------------
#define BSZ   8
#define CIN   256
#define NYv   80
#define NXv   80
#define CC    256
#define HW    (NYv * NXv)        // 6400
#define NPIX  (BSZ * HW)         // 51200
#define NPTS  16384
#define KD    (CC * 9)           // 2304  (conv K, single-term fp16)
#define NOUT  85

// ---------------- device scratch ----------------
__device__ __align__(16) __half g_x[(size_t)NPIX * CIN];    // x transposed, fp16
__device__ __align__(16) __half g_s[(size_t)NPIX * CC];     // stem out, channel-last fp16
__device__ __align__(16) __half g_sw[(size_t)CC * CIN];     // stem W fp16 [o][c]
__device__ __align__(16) __half g_cw[(size_t)512 * KD];     // conv W fp16 [o512][q*256+c]
__device__ __align__(16) float g_feat[(size_t)2 * NPTS * CC];   // set0=cls, set1=reg
__device__ __align__(16) float g_predw[96 * 256];
__device__ float g_predb[96];
__device__ int   g_sb[NPTS], g_sy[NPTS], g_sx[NPTS];

__device__ __forceinline__ float silu(float v) {
    return v * (1.0f / (1.0f + __expf(-v)));
}

// ================= warp MMA primitives =================
__device__ __forceinline__ void mma16816(float* d, const uint32_t* a, uint32_t b0, uint32_t b1) {
    asm volatile(
        "mma.sync.aligned.m16n8k16.row.col.f32.f16.f16.f32 "
        "{%0,%1,%2,%3}, {%4,%5,%6,%7}, {%8,%9}, {%0,%1,%2,%3};"
        : "+f"(d[0]), "+f"(d[1]), "+f"(d[2]), "+f"(d[3])
        : "r"(a[0]), "r"(a[1]), "r"(a[2]), "r"(a[3]), "r"(b0), "r"(b1));
}
__device__ __forceinline__ void ldsm4(uint32_t* r, uint32_t addr) {
    asm volatile("ldmatrix.sync.aligned.m8n8.x4.shared.b16 {%0,%1,%2,%3}, [%4];"
        : "=r"(r[0]), "=r"(r[1]), "=r"(r[2]), "=r"(r[3]) : "r"(addr));
}
__device__ __forceinline__ uint32_t smem_u32(const void* p) {
    uint32_t a;
    asm("{ .reg .u64 t; cvta.to.shared.u64 t, %1; cvt.u32.u64 %0, t; }" : "=r"(a) : "l"(p));
    return a;
}

// ---- smem rows: 64 halves = 128B, xor swizzle on 16B chunks ----
#define A_TILE 16384             // 128 rows
#define B_TILE_CONV 32768        // 256 rows
#define CV_SMEM (3 * A_TILE + 3 * B_TILE_CONV)   // 144KB, 3-stage
#define ST_SMEM (4 * A_TILE)                      // 64KB, 2-stage

// One 64-deep K stage for one warp (tile 64x32), acc[4][4][4].
__device__ __forceinline__ void compute_stage(uint32_t abase, uint32_t bbase,
                                              int wm, int wn, int lane,
                                              float acc[4][4][4]) {
    const int ar = lane & 15, ac = lane >> 4;
    const int bn = (lane & 7) + ((lane >> 4) << 3);
    const int bk = (lane >> 3) & 1;
    #pragma unroll
    for (int ks = 0; ks < 4; ks++) {
        uint32_t a[4][4], b[2][4];
        #pragma unroll
        for (int i = 0; i < 4; i++) {
            int row = wm * 64 + i * 16 + ar;
            int ch  = (ks * 2 + ac) ^ (row & 7);
            ldsm4(a[i], abase + row * 128 + ch * 16);
        }
        #pragma unroll
        for (int j = 0; j < 2; j++) {
            int n  = wn * 32 + j * 16 + bn;
            int ch = (ks * 2 + bk) ^ (n & 7);
            ldsm4(b[j], bbase + n * 128 + ch * 16);
        }
        #pragma unroll
        for (int i = 0; i < 4; i++)
            #pragma unroll
            for (int jj = 0; jj < 4; jj++)
                mma16816(acc[i][jj], a[i], b[jj >> 1][(jj & 1) * 2], b[jj >> 1][(jj & 1) * 2 + 1]);
    }
}

// ================= Kernel 0: decode indices (int64/int32 autodetect) ========
__global__ void decode_indices(const int* __restrict__ idx32) {
    int n = blockIdx.x * blockDim.x + threadIdx.x;
    if (n >= NPTS) return;
    bool is64 = true;
    #pragma unroll
    for (int k = 1; k < 24; k += 2) is64 = is64 && (idx32[k] == 0);
    int bi, yi, xi;
    if (is64) { bi = idx32[6 * n]; yi = idx32[6 * n + 2]; xi = idx32[6 * n + 4]; }
    else      { bi = idx32[3 * n]; yi = idx32[3 * n + 1]; xi = idx32[3 * n + 2]; }
    g_sb[n] = bi; g_sy[n] = yi; g_sx[n] = xi;
}

// ================= prep kernels =================
__global__ void prep_x(const float* __restrict__ x) {
    __shared__ float t[32][33];
    int p0 = blockIdx.x * 32, c0 = blockIdx.y * 32, b = blockIdx.z;
    int tx = threadIdx.x, ty = threadIdx.y;
    #pragma unroll
    for (int j = 0; j < 4; j++) {
        int c = c0 + ty + j * 8;
        t[ty + j * 8][tx] = x[((size_t)b * CIN + c) * HW + p0 + tx];
    }
    __syncthreads();
    #pragma unroll
    for (int j = 0; j < 4; j++) {
        int p = p0 + ty + j * 8;
        g_x[((size_t)b * HW + p) * CIN + c0 + tx] = __float2half_rn(t[tx][ty + j * 8]);
    }
}

__global__ void prep_sw(const float* __restrict__ w) {
    int idx = blockIdx.x * blockDim.x + threadIdx.x;
    if (idx >= CC * CIN) return;
    g_sw[idx] = __float2half_rn(w[idx]);
}

// conv W fp16: [o512][q*256+c], korig = c*9+q
__global__ void prep_cw(const float* __restrict__ wc, const float* __restrict__ wr) {
    size_t idx = (size_t)blockIdx.x * blockDim.x + threadIdx.x;
    if (idx >= (size_t)512 * KD) return;
    int o = (int)(idx / KD), r = (int)(idx % KD);
    int q = r >> 8, c = r & 255;
    int korig = c * 9 + q;
    float v = (o < 256) ? wc[(size_t)o * KD + korig] : wr[(size_t)(o - 256) * KD + korig];
    g_cw[idx] = __float2half_rn(v);
}

__global__ void prep_pw(const float* __restrict__ cw, const float* __restrict__ cb,
                        const float* __restrict__ rw, const float* __restrict__ rb,
                        const float* __restrict__ ow, const float* __restrict__ ob) {
    int idx = blockIdx.x * blockDim.x + threadIdx.x;
    if (idx >= 96 * 256) return;
    int o = idx / 256, k = idx % 256;
    float v = 0.f;
    if (o < 4)       v = rw[o * 256 + k];
    else if (o == 4) v = ow[k];
    else if (o < 85) v = cw[(o - 5) * 256 + k];
    g_predw[idx] = v;
    if (k == 0) {
        float bv = 0.f;
        if (o < 4) bv = rb[o]; else if (o == 4) bv = ob[0]; else if (o < 85) bv = cb[o - 5];
        g_predb[o] = bv;
    }
}

// ================= stem GEMM (single-term fp16, 2-stage) =================
// grid (400, 2), 256 thr. M=128 pixels, N=128 outs, K=256 (4 stages).
__global__ __launch_bounds__(256) void stem_gemm(const float* __restrict__ bias) {
    extern __shared__ char sm[];
    uint32_t smb = smem_u32(sm);
    int tid = threadIdx.x, lane = tid & 31, wid = tid >> 5;
    int wm = wid & 1, wn = wid >> 1;
    int m0 = blockIdx.x * 128;
    int oB = blockIdx.y * 128;

    float acc[4][4][4] = {};
    const int NCH = CIN / 64;   // 4

    auto load_stage = [&](int buf, int i) {
        int kc = i * 64;
        char* A = sm + buf * A_TILE;
        char* B = sm + 2 * A_TILE + buf * A_TILE;
        #pragma unroll
        for (int j2 = 0; j2 < 4; j2++) {
            int l = tid + 256 * j2;
            int row = l >> 3, ch = l & 7;
            int sw = (ch ^ (row & 7)) * 16 + row * 128;
            __pipeline_memcpy_async(A + sw, g_x + ((size_t)(m0 + row) * CIN + kc + ch * 8), 16);
            __pipeline_memcpy_async(B + sw, g_sw + ((size_t)(oB + row) * CIN + kc + ch * 8), 16);
        }
    };

    load_stage(0, 0); __pipeline_commit();
    for (int i = 0; i < NCH; i++) {
        int buf = i & 1;
        if (i + 1 < NCH) {
            load_stage(buf ^ 1, i + 1); __pipeline_commit();
            __pipeline_wait_prior(1);
        } else {
            __pipeline_wait_prior(0);
        }
        __syncthreads();
        compute_stage(smb + buf * A_TILE, smb + 2 * A_TILE + buf * A_TILE,
                      wm, wn, lane, acc);
        __syncthreads();
    }

    int g = lane >> 2, tg = lane & 3;
    #pragma unroll
    for (int i = 0; i < 4; i++) {
        #pragma unroll
        for (int jj = 0; jj < 4; jj++) {
            int col = oB + wn * 32 + jj * 8 + tg * 2;
            float b0 = bias[col], b1 = bias[col + 1];
            int r0 = m0 + wm * 64 + i * 16 + g;
            #pragma unroll
            for (int h = 0; h < 2; h++) {
                int pix = r0 + h * 8;
                __half2 hp;
                hp.x = __float2half_rn(silu(acc[i][jj][h * 2 + 0] + b0));
                hp.y = __float2half_rn(silu(acc[i][jj][h * 2 + 1] + b1));
                *(__half2*)&g_s[(size_t)pix * CC + col] = hp;
            }
        }
    }
}

// ================= conv GEMM (single-term fp16, fused gather, 3-stage) =====
// grid (128, 2), 512 thr (16 warps). M=128 pts, N=256 outs, K=2304 (36 stages).
__global__ __launch_bounds__(512) void conv_gemm(const float* __restrict__ bc,
                                                 const float* __restrict__ br) {
    extern __shared__ char sm[];
    __shared__ int ssb[128], ssy[128], ssx[128];
    uint32_t smb = smem_u32(sm);
    int tid = threadIdx.x, lane = tid & 31, wid = tid >> 5;
    int wm = wid & 1, wn = wid >> 1;       // wn 0..7
    int n0 = blockIdx.x * 128;
    int oB = blockIdx.y * 256;

    if (tid < 128) { ssb[tid] = g_sb[n0 + tid]; ssy[tid] = g_sy[n0 + tid]; ssx[tid] = g_sx[n0 + tid]; }
    __syncthreads();

    float acc[4][4][4] = {};
    const int NCH = KD / 64;   // 36

    auto load_stage = [&](int buf, int i) {
        int kc = i * 64;
        int q = kc >> 8, c0 = kc & 255;
        int kh = q / 3, kw = q - kh * 3;
        char* A = sm + buf * A_TILE;
        char* B = sm + 3 * A_TILE + buf * B_TILE_CONV;
        // A: 128 rows -> 1024 chunks / 512 thr = 2 each
        #pragma unroll
        for (int j2 = 0; j2 < 2; j2++) {
            int l = tid + 512 * j2;
            int row = l >> 3, ch = l & 7;
            int sw = (ch ^ (row & 7)) * 16 + row * 128;
            int y = ssy[row] + kh - 1, xx = ssx[row] + kw - 1;
            bool ok = ((unsigned)y < (unsigned)NYv) && ((unsigned)xx < (unsigned)NXv);
            const __half* gp = g_s +
                ((((size_t)ssb[row] * NYv + (ok ? y : 0)) * NXv + (ok ? xx : 0)) * CC + c0 + ch * 8);
            __pipeline_memcpy_async(A + sw, gp, 16, ok ? 0 : 16);   // zfill when OOB
        }
        // B: 256 rows -> 2048 chunks / 512 thr = 4 each
        #pragma unroll
        for (int j2 = 0; j2 < 4; j2++) {
            int l = tid + 512 * j2;
            int row = l >> 3, ch = l & 7;
            int sw = (ch ^ (row & 7)) * 16 + row * 128;
            __pipeline_memcpy_async(B + sw, g_cw + ((size_t)(oB + row) * KD + kc + ch * 8), 16);
        }
    };

    load_stage(0, 0); __pipeline_commit();
    load_stage(1, 1); __pipeline_commit();
    for (int i = 0; i < NCH; i++) {
        int buf = i % 3;
        if (i + 2 < NCH) {
            load_stage((i + 2) % 3, i + 2); __pipeline_commit();
            __pipeline_wait_prior(2);
        } else if (i + 1 < NCH) {
            __pipeline_wait_prior(1);
        } else {
            __pipeline_wait_prior(0);
        }
        __syncthreads();
        compute_stage(smb + buf * A_TILE, smb + 3 * A_TILE + buf * B_TILE_CONV,
                      wm, wn, lane, acc);
        __syncthreads();
    }

    int g = lane >> 2, tg = lane & 3;
    #pragma unroll
    for (int i = 0; i < 4; i++) {
        #pragma unroll
        for (int jj = 0; jj < 4; jj++) {
            int col = oB + wn * 32 + jj * 8 + tg * 2;
            int set = col >> 8, o = col & 255;
            const float* bp = set ? br : bc;
            float b0 = bp[o], b1 = bp[o + 1];
            int r0 = n0 + wm * 64 + i * 16 + g;
            float2 v;
            v.x = silu(acc[i][jj][0] + b0); v.y = silu(acc[i][jj][1] + b1);
            *(float2*)&g_feat[((size_t)set * NPTS + r0) * CC + o] = v;
            v.x = silu(acc[i][jj][2] + b0); v.y = silu(acc[i][jj][3] + b1);
            *(float2*)&g_feat[((size_t)set * NPTS + r0 + 8) * CC + o] = v;
        }
    }
}

// ================= pred heads =================
__global__ __launch_bounds__(384) void pred_kernel(float* __restrict__ out) {
    __shared__ float sfeat[512];
    int tid = threadIdx.x, wq = tid >> 5, lane = tid & 31;
    int obase = wq * 8;
    int n0 = blockIdx.x * 32;

    float wreg[8][8], bj[8];
    #pragma unroll
    for (int j = 0; j < 8; j++) {
        bj[j] = g_predb[obase + j];
        #pragma unroll
        for (int seg = 0; seg < 8; seg++)
            wreg[j][seg] = g_predw[(obase + j) * 256 + seg * 32 + lane];
    }

    for (int r = 0; r < 32; r++) {
        int n = n0 + r;
        for (int i = tid; i < 512; i += 384) {
            int set = i >> 8, k = i & 255;
            sfeat[i] = g_feat[((size_t)set * NPTS + n) * CC + k];
        }
        __syncthreads();
        float cf[8], rf[8];
        #pragma unroll
        for (int seg = 0; seg < 8; seg++) {
            cf[seg] = sfeat[seg * 32 + lane];
            rf[seg] = sfeat[256 + seg * 32 + lane];
        }
        #pragma unroll
        for (int j = 0; j < 8; j++) {
            bool useReg = (obase + j) < 5;
            float s = 0.f;
            #pragma unroll
            for (int seg = 0; seg < 8; seg++)
                s = fmaf(useReg ? rf[seg] : cf[seg], wreg[j][seg], s);
            #pragma unroll
            for (int off = 16; off > 0; off >>= 1)
                s += __shfl_xor_sync(0xffffffffu, s, off);
            int o = obase + j;
            if (lane == 0 && o < NOUT) out[(size_t)n * NOUT + o] = s + bj[j];
        }
        __syncthreads();
    }
}

// ================= launch =================
extern "C" void kernel_launch(void* const* d_in, const int* in_sizes, int n_in,
                              void* d_out, int out_size) {
    const float* x          = (const float*)d_in[0];
    const int*   indices32  = (const int*)d_in[1];
    const float* stem_w     = (const float*)d_in[2];
    const float* stem_b     = (const float*)d_in[3];
    const float* cls_conv_w = (const float*)d_in[4];
    const float* cls_conv_b = (const float*)d_in[5];
    const float* reg_conv_w = (const float*)d_in[6];
    const float* reg_conv_b = (const float*)d_in[7];
    const float* cls_pred_w = (const float*)d_in[8];
    const float* cls_pred_b = (const float*)d_in[9];
    const float* reg_pred_w = (const float*)d_in[10];
    const float* reg_pred_b = (const float*)d_in[11];
    const float* obj_pred_w = (const float*)d_in[12];
    const float* obj_pred_b = (const float*)d_in[13];
    float* out = (float*)d_out;

    cudaFuncSetAttribute(stem_gemm, cudaFuncAttributeMaxDynamicSharedMemorySize, ST_SMEM);
    cudaFuncSetAttribute(conv_gemm, cudaFuncAttributeMaxDynamicSharedMemorySize, CV_SMEM);

    decode_indices<<<NPTS / 256, 256>>>(indices32);

    dim3 gx(HW / 32, CIN / 32, BSZ);
    prep_x<<<gx, dim3(32, 8)>>>(x);
    prep_sw<<<(CC * CIN + 255) / 256, 256>>>(stem_w);
    prep_cw<<<(int)(((size_t)512 * KD + 255) / 256), 256>>>(cls_conv_w, reg_conv_w);
    prep_pw<<<(96 * 256 + 255) / 256, 256>>>(cls_pred_w, cls_pred_b,
                                             reg_pred_w, reg_pred_b,
                                             obj_pred_w, obj_pred_b);

    stem_gemm<<<dim3(NPIX / 128, 2), 256, ST_SMEM>>>(stem_b);
    conv_gemm<<<dim3(NPTS / 128, 2), 512, CV_SMEM>>>(cls_conv_b, reg_conv_b);
    pred_kernel<<<NPTS / 32, 384>>>(out);
}

// round 9
// speedup vs baseline: 10.2302x; 1.9163x over previous
#include <cuda_runtime.h>
#include <cuda_fp16.h>
#include <cuda_pipeline.h>
#include <stdint.h>

// ---------------- problem constants ----------------
#define BSZ   8
#define CIN   256
#define NYv   80
#define NXv   80
#define CC    256
#define HW    (NYv * NXv)        // 6400
#define NPIX  (BSZ * HW)         // 51200
#define NPTS  16384
#define KD    (CC * 9)           // 2304
#define NOUT  85

// ---------------- device scratch ----------------
__device__ __align__(16) __half g_x[(size_t)NPIX * CIN];       // x transposed fp16
__device__ __align__(16) __half g_s[(size_t)NPIX * CC];        // stem out fp16 channel-last
__device__ __align__(16) __half g_sw[(size_t)CC * CIN];        // stem W fp16 [o][c]
__device__ __align__(16) __half g_cw[(size_t)512 * KD];        // conv W fp16 [o512][q*256+c]
__device__ __align__(16) __half g_featH[(size_t)NPTS * 512];   // [n][cls256|reg256] fp16
__device__ __align__(16) __half g_predw2[128 * 512];           // padded pred W fp16
__device__ float g_predb[128];
__device__ int   g_sb[NPTS], g_sy[NPTS], g_sx[NPTS];

__device__ __forceinline__ float silu(float v) {
    return v * (1.0f / (1.0f + __expf(-v)));
}

// ================= warp MMA primitives =================
__device__ __forceinline__ void mma16816(float* d, const uint32_t* a, uint32_t b0, uint32_t b1) {
    asm volatile(
        "mma.sync.aligned.m16n8k16.row.col.f32.f16.f16.f32 "
        "{%0,%1,%2,%3}, {%4,%5,%6,%7}, {%8,%9}, {%0,%1,%2,%3};"
        : "+f"(d[0]), "+f"(d[1]), "+f"(d[2]), "+f"(d[3])
        : "r"(a[0]), "r"(a[1]), "r"(a[2]), "r"(a[3]), "r"(b0), "r"(b1));
}
__device__ __forceinline__ void ldsm4(uint32_t* r, uint32_t addr) {
    asm volatile("ldmatrix.sync.aligned.m8n8.x4.shared.b16 {%0,%1,%2,%3}, [%4];"
        : "=r"(r[0]), "=r"(r[1]), "=r"(r[2]), "=r"(r[3]) : "r"(addr));
}
__device__ __forceinline__ uint32_t smem_u32(const void* p) {
    uint32_t a;
    asm("{ .reg .u64 t; cvta.to.shared.u64 t, %1; cvt.u32.u64 %0, t; }" : "=r"(a) : "l"(p));
    return a;
}

// ---- smem rows: 64 halves = 128B, xor swizzle on 16B chunks ----
#define A_TILE 16384             // 128 rows
#define B_TILE 32768             // 256 rows
#define CV_SMEM (3 * A_TILE + 3 * B_TILE)   // conv: 3-stage, 144KB
#define ST_SMEM (2 * A_TILE + 2 * B_TILE)   // stem: 2-stage, 96KB
#define PR_SMEM (4 * A_TILE)                // pred: 2-stage, 64KB (B=128 rows)

// One 64-deep K stage for one warp (tile 64x32), acc[4][4][4].
__device__ __forceinline__ void compute_stage(uint32_t abase, uint32_t bbase,
                                              int wm, int wn, int lane,
                                              float acc[4][4][4]) {
    const int ar = lane & 15, ac = lane >> 4;
    const int bn = (lane & 7) + ((lane >> 4) << 3);
    const int bk = (lane >> 3) & 1;
    #pragma unroll
    for (int ks = 0; ks < 4; ks++) {
        uint32_t a[4][4], b[2][4];
        #pragma unroll
        for (int i = 0; i < 4; i++) {
            int row = wm * 64 + i * 16 + ar;
            int ch  = (ks * 2 + ac) ^ (row & 7);
            ldsm4(a[i], abase + row * 128 + ch * 16);
        }
        #pragma unroll
        for (int j = 0; j < 2; j++) {
            int n  = wn * 32 + j * 16 + bn;
            int ch = (ks * 2 + bk) ^ (n & 7);
            ldsm4(b[j], bbase + n * 128 + ch * 16);
        }
        #pragma unroll
        for (int i = 0; i < 4; i++)
            #pragma unroll
            for (int jj = 0; jj < 4; jj++)
                mma16816(acc[i][jj], a[i], b[jj >> 1][(jj & 1) * 2], b[jj >> 1][(jj & 1) * 2 + 1]);
    }
}

// ================= Kernel 0: decode indices (int64/int32 autodetect) ========
__global__ void decode_indices(const int* __restrict__ idx32) {
    int n = blockIdx.x * blockDim.x + threadIdx.x;
    if (n >= NPTS) return;
    bool is64 = true;
    #pragma unroll
    for (int k = 1; k < 24; k += 2) is64 = is64 && (idx32[k] == 0);
    int bi, yi, xi;
    if (is64) { bi = idx32[6 * n]; yi = idx32[6 * n + 2]; xi = idx32[6 * n + 4]; }
    else      { bi = idx32[3 * n]; yi = idx32[3 * n + 1]; xi = idx32[3 * n + 2]; }
    g_sb[n] = bi; g_sy[n] = yi; g_sx[n] = xi;
}

// ================= prep kernels =================
__global__ void prep_x(const float* __restrict__ x) {
    __shared__ float t[32][33];
    int p0 = blockIdx.x * 32, c0 = blockIdx.y * 32, b = blockIdx.z;
    int tx = threadIdx.x, ty = threadIdx.y;
    #pragma unroll
    for (int j = 0; j < 4; j++) {
        int c = c0 + ty + j * 8;
        t[ty + j * 8][tx] = x[((size_t)b * CIN + c) * HW + p0 + tx];
    }
    __syncthreads();
    #pragma unroll
    for (int j = 0; j < 4; j++) {
        int p = p0 + ty + j * 8;
        g_x[((size_t)b * HW + p) * CIN + c0 + tx] = __float2half_rn(t[tx][ty + j * 8]);
    }
}

__global__ void prep_sw(const float* __restrict__ w) {
    int idx = blockIdx.x * blockDim.x + threadIdx.x;
    if (idx >= CC * CIN) return;
    g_sw[idx] = __float2half_rn(w[idx]);
}

// conv W fp16: [o512][q*256+c], korig = c*9+q
__global__ void prep_cw(const float* __restrict__ wc, const float* __restrict__ wr) {
    size_t idx = (size_t)blockIdx.x * blockDim.x + threadIdx.x;
    if (idx >= (size_t)512 * KD) return;
    int o = (int)(idx / KD), r = (int)(idx % KD);
    int q = r >> 8, c = r & 255;
    int korig = c * 9 + q;
    float v = (o < 256) ? wc[(size_t)o * KD + korig] : wr[(size_t)(o - 256) * KD + korig];
    g_cw[idx] = __float2half_rn(v);
}

// padded pred weights: row o, cols [cls256 | reg256]:
//   o<4: reg weights in cols 256+; o==4: obj in cols 256+; 5<=o<85: cls in cols 0-255.
__global__ void prep_pw(const float* __restrict__ cw, const float* __restrict__ cb,
                        const float* __restrict__ rw, const float* __restrict__ rb,
                        const float* __restrict__ ow, const float* __restrict__ ob) {
    int idx = blockIdx.x * blockDim.x + threadIdx.x;
    if (idx >= 128 * 512) return;
    int o = idx >> 9, k = idx & 511;
    float v = 0.f;
    if (o < 4)       { if (k >= 256) v = rw[o * 256 + (k - 256)]; }
    else if (o == 4) { if (k >= 256) v = ow[k - 256]; }
    else if (o < 85) { if (k < 256)  v = cw[(o - 5) * 256 + k]; }
    g_predw2[idx] = __float2half_rn(v);
    if (k == 0) {
        float bv = 0.f;
        if (o < 4) bv = rb[o]; else if (o == 4) bv = ob[0]; else if (o < 85) bv = cb[o - 5];
        g_predb[o] = bv;
    }
}

// ================= stem GEMM (fp16, 2-stage, N=256) =================
// grid 400, 512 thr (16 warps). M=128 pixels, N=256 outs, K=256 (4 stages).
__global__ __launch_bounds__(512) void stem_gemm(const float* __restrict__ bias) {
    extern __shared__ char sm[];
    uint32_t smb = smem_u32(sm);
    int tid = threadIdx.x, lane = tid & 31, wid = tid >> 5;
    int wm = wid & 1, wn = wid >> 1;    // wn 0..7
    int m0 = blockIdx.x * 128;

    float acc[4][4][4] = {};
    const int NCH = CIN / 64;   // 4

    auto load_stage = [&](int buf, int i) {
        int kc = i * 64;
        char* A = sm + buf * A_TILE;
        char* B = sm + 2 * A_TILE + buf * B_TILE;
        #pragma unroll
        for (int j2 = 0; j2 < 2; j2++) {
            int l = tid + 512 * j2;
            int row = l >> 3, ch = l & 7;
            int sw = (ch ^ (row & 7)) * 16 + row * 128;
            __pipeline_memcpy_async(A + sw, g_x + ((size_t)(m0 + row) * CIN + kc + ch * 8), 16);
        }
        #pragma unroll
        for (int j2 = 0; j2 < 4; j2++) {
            int l = tid + 512 * j2;
            int row = l >> 3, ch = l & 7;
            int sw = (ch ^ (row & 7)) * 16 + row * 128;
            __pipeline_memcpy_async(B + sw, g_sw + ((size_t)row * CIN + kc + ch * 8), 16);
        }
    };

    load_stage(0, 0); __pipeline_commit();
    for (int i = 0; i < NCH; i++) {
        __pipeline_wait_prior(0);
        __syncthreads();
        if (i + 1 < NCH) { load_stage((i + 1) & 1, i + 1); __pipeline_commit(); }
        compute_stage(smb + (i & 1) * A_TILE, smb + 2 * A_TILE + (i & 1) * B_TILE,
                      wm, wn, lane, acc);
    }

    int g = lane >> 2, tg = lane & 3;
    #pragma unroll
    for (int i = 0; i < 4; i++) {
        #pragma unroll
        for (int jj = 0; jj < 4; jj++) {
            int col = wn * 32 + jj * 8 + tg * 2;
            float b0 = bias[col], b1 = bias[col + 1];
            int r0 = m0 + wm * 64 + i * 16 + g;
            #pragma unroll
            for (int h = 0; h < 2; h++) {
                int pix = r0 + h * 8;
                __half2 hp;
                hp.x = __float2half_rn(silu(acc[i][jj][h * 2 + 0] + b0));
                hp.y = __float2half_rn(silu(acc[i][jj][h * 2 + 1] + b1));
                *(__half2*)&g_s[(size_t)pix * CC + col] = hp;
            }
        }
    }
}

// ================= conv GEMM (fp16, fused gather, 3-stage) =====
// grid (128, 2), 512 thr (16 warps). M=128 pts, N=256 outs, K=2304 (36 stages).
__global__ __launch_bounds__(512) void conv_gemm(const float* __restrict__ bc,
                                                 const float* __restrict__ br) {
    extern __shared__ char sm[];
    __shared__ int ssb[128], ssy[128], ssx[128];
    uint32_t smb = smem_u32(sm);
    int tid = threadIdx.x, lane = tid & 31, wid = tid >> 5;
    int wm = wid & 1, wn = wid >> 1;       // wn 0..7
    int n0 = blockIdx.x * 128;
    int set = blockIdx.y;                  // 0=cls, 1=reg
    int oB = set * 256;

    if (tid < 128) { ssb[tid] = g_sb[n0 + tid]; ssy[tid] = g_sy[n0 + tid]; ssx[tid] = g_sx[n0 + tid]; }
    __syncthreads();

    float acc[4][4][4] = {};
    const int NCH = KD / 64;   // 36

    auto load_stage = [&](int buf, int i) {
        int kc = i * 64;
        int q = kc >> 8, c0 = kc & 255;
        int kh = q / 3, kw = q - kh * 3;
        char* A = sm + buf * A_TILE;
        char* B = sm + 3 * A_TILE + buf * B_TILE;
        #pragma unroll
        for (int j2 = 0; j2 < 2; j2++) {
            int l = tid + 512 * j2;
            int row = l >> 3, ch = l & 7;
            int sw = (ch ^ (row & 7)) * 16 + row * 128;
            int y = ssy[row] + kh - 1, xx = ssx[row] + kw - 1;
            bool ok = ((unsigned)y < (unsigned)NYv) && ((unsigned)xx < (unsigned)NXv);
            const __half* gp = g_s +
                ((((size_t)ssb[row] * NYv + (ok ? y : 0)) * NXv + (ok ? xx : 0)) * CC + c0 + ch * 8);
            __pipeline_memcpy_async(A + sw, gp, 16, ok ? 0 : 16);   // zfill when OOB
        }
        #pragma unroll
        for (int j2 = 0; j2 < 4; j2++) {
            int l = tid + 512 * j2;
            int row = l >> 3, ch = l & 7;
            int sw = (ch ^ (row & 7)) * 16 + row * 128;
            __pipeline_memcpy_async(B + sw, g_cw + ((size_t)(oB + row) * KD + kc + ch * 8), 16);
        }
    };

    load_stage(0, 0); __pipeline_commit();
    load_stage(1, 1); __pipeline_commit();
    for (int i = 0; i < NCH; i++) {
        if (i == NCH - 1) { __pipeline_wait_prior(0); } else { __pipeline_wait_prior(1); }
        __syncthreads();
        if (i + 2 < NCH) { load_stage((i + 2) % 3, i + 2); __pipeline_commit(); }
        compute_stage(smb + (i % 3) * A_TILE, smb + 3 * A_TILE + (i % 3) * B_TILE,
                      wm, wn, lane, acc);
    }

    const float* bp = set ? br : bc;
    int g = lane >> 2, tg = lane & 3;
    #pragma unroll
    for (int i = 0; i < 4; i++) {
        #pragma unroll
        for (int jj = 0; jj < 4; jj++) {
            int col = wn * 32 + jj * 8 + tg * 2;      // 0..255 within set
            float b0 = bp[col], b1 = bp[col + 1];
            int r0 = n0 + wm * 64 + i * 16 + g;
            #pragma unroll
            for (int h = 0; h < 2; h++) {
                int n = r0 + h * 8;
                __half2 hp;
                hp.x = __float2half_rn(silu(acc[i][jj][h * 2 + 0] + b0));
                hp.y = __float2half_rn(silu(acc[i][jj][h * 2 + 1] + b1));
                *(__half2*)&g_featH[(size_t)n * 512 + set * 256 + col] = hp;
            }
        }
    }
}

// ================= pred GEMM (fp16 mma) =================
// grid 128, 256 thr (8 warps: 2x4). M=128 pts, N=128 (85 used), K=512 (8 stages).
__global__ __launch_bounds__(256) void pred_gemm(float* __restrict__ out) {
    extern __shared__ char sm[];
    uint32_t smb = smem_u32(sm);
    int tid = threadIdx.x, lane = tid & 31, wid = tid >> 5;
    int wm = wid & 1, wn = wid >> 1;    // wn 0..3
    int n0 = blockIdx.x * 128;

    float acc[4][4][4] = {};
    const int NCH = 512 / 64;   // 8

    auto load_stage = [&](int buf, int i) {
        int kc = i * 64;
        char* A = sm + buf * A_TILE;
        char* B = sm + 2 * A_TILE + buf * A_TILE;   // B tile 128 rows = 16KB
        #pragma unroll
        for (int j2 = 0; j2 < 4; j2++) {
            int l = tid + 256 * j2;
            int row = l >> 3, ch = l & 7;
            int sw = (ch ^ (row & 7)) * 16 + row * 128;
            __pipeline_memcpy_async(A + sw, g_featH + ((size_t)(n0 + row) * 512 + kc + ch * 8), 16);
            __pipeline_memcpy_async(B + sw, g_predw2 + ((size_t)row * 512 + kc + ch * 8), 16);
        }
    };

    load_stage(0, 0); __pipeline_commit();
    for (int i = 0; i < NCH; i++) {
        __pipeline_wait_prior(0);
        __syncthreads();
        if (i + 1 < NCH) { load_stage((i + 1) & 1, i + 1); __pipeline_commit(); }
        compute_stage(smb + (i & 1) * A_TILE, smb + 2 * A_TILE + (i & 1) * A_TILE,
                      wm, wn, lane, acc);
    }

    int g = lane >> 2, tg = lane & 3;
    #pragma unroll
    for (int i = 0; i < 4; i++) {
        #pragma unroll
        for (int jj = 0; jj < 4; jj++) {
            int col = wn * 32 + jj * 8 + tg * 2;     // 0..127
            int r0 = n0 + wm * 64 + i * 16 + g;
            if (col < NOUT) {
                float bv = g_predb[col];
                out[(size_t)r0 * NOUT + col]       = acc[i][jj][0] + bv;
                out[(size_t)(r0 + 8) * NOUT + col] = acc[i][jj][2] + bv;
            }
            if (col + 1 < NOUT) {
                float bv = g_predb[col + 1];
                out[(size_t)r0 * NOUT + col + 1]       = acc[i][jj][1] + bv;
                out[(size_t)(r0 + 8) * NOUT + col + 1] = acc[i][jj][3] + bv;
            }
        }
    }
}

// ================= launch =================
extern "C" void kernel_launch(void* const* d_in, const int* in_sizes, int n_in,
                              void* d_out, int out_size) {
    const float* x          = (const float*)d_in[0];
    const int*   indices32  = (const int*)d_in[1];
    const float* stem_w     = (const float*)d_in[2];
    const float* stem_b     = (const float*)d_in[3];
    const float* cls_conv_w = (const float*)d_in[4];
    const float* cls_conv_b = (const float*)d_in[5];
    const float* reg_conv_w = (const float*)d_in[6];
    const float* reg_conv_b = (const float*)d_in[7];
    const float* cls_pred_w = (const float*)d_in[8];
    const float* cls_pred_b = (const float*)d_in[9];
    const float* reg_pred_w = (const float*)d_in[10];
    const float* reg_pred_b = (const float*)d_in[11];
    const float* obj_pred_w = (const float*)d_in[12];
    const float* obj_pred_b = (const float*)d_in[13];
    float* out = (float*)d_out;

    cudaFuncSetAttribute(stem_gemm, cudaFuncAttributeMaxDynamicSharedMemorySize, ST_SMEM);
    cudaFuncSetAttribute(conv_gemm, cudaFuncAttributeMaxDynamicSharedMemorySize, CV_SMEM);
    cudaFuncSetAttribute(pred_gemm, cudaFuncAttributeMaxDynamicSharedMemorySize, PR_SMEM);

    decode_indices<<<NPTS / 256, 256>>>(indices32);

    dim3 gx(HW / 32, CIN / 32, BSZ);
    prep_x<<<gx, dim3(32, 8)>>>(x);
    prep_sw<<<(CC * CIN + 255) / 256, 256>>>(stem_w);
    prep_cw<<<(int)(((size_t)512 * KD + 255) / 256), 256>>>(cls_conv_w, reg_conv_w);
    prep_pw<<<(128 * 512 + 255) / 256, 256>>>(cls_pred_w, cls_pred_b,
                                              reg_pred_w, reg_pred_b,
                                              obj_pred_w, obj_pred_b);

    stem_gemm<<<NPIX / 128, 512, ST_SMEM>>>(stem_b);
    conv_gemm<<<dim3(NPTS / 128, 2), 512, CV_SMEM>>>(cls_conv_b, reg_conv_b);
    pred_gemm<<<NPTS / 128, 256, PR_SMEM>>>(out);
}

// round 10
// speedup vs baseline: 10.5237x; 1.0287x over previous
#include <cuda_runtime.h>
#include <cuda_fp16.h>
#include <cuda_pipeline.h>
#include <stdint.h>

// ---------------- problem constants ----------------
#define BSZ   8
#define CIN   256
#define NYv   80
#define NXv   80
#define CC    256
#define HW    (NYv * NXv)        // 6400
#define NPIX  (BSZ * HW)         // 51200
#define NPTS  16384
#define KD    (CC * 9)           // 2304
#define NOUT  85

// ---------------- device scratch ----------------
__device__ __align__(16) __half g_x[(size_t)NPIX * CIN];       // x transposed fp16
__device__ __align__(16) __half g_s[(size_t)NPIX * CC];        // stem out fp16 channel-last
__device__ __align__(16) __half g_sw[(size_t)CC * CIN];        // stem W fp16 [o][c]
__device__ __align__(16) __half g_cw[(size_t)512 * KD];        // conv W fp16 [o512][q*256+c]
__device__ __align__(16) __half g_featH[(size_t)NPTS * 512];   // [n][cls256|reg256] fp16
__device__ __align__(16) __half g_predw2[128 * 512];           // padded pred W fp16
__device__ float g_predb[128];
__device__ int   g_sb[NPTS], g_sy[NPTS], g_sx[NPTS];

__device__ __forceinline__ float silu(float v) {
    return v * (1.0f / (1.0f + __expf(-v)));
}

// ================= warp MMA primitives =================
__device__ __forceinline__ void mma16816(float* d, const uint32_t* a, uint32_t b0, uint32_t b1) {
    asm volatile(
        "mma.sync.aligned.m16n8k16.row.col.f32.f16.f16.f32 "
        "{%0,%1,%2,%3}, {%4,%5,%6,%7}, {%8,%9}, {%0,%1,%2,%3};"
        : "+f"(d[0]), "+f"(d[1]), "+f"(d[2]), "+f"(d[3])
        : "r"(a[0]), "r"(a[1]), "r"(a[2]), "r"(a[3]), "r"(b0), "r"(b1));
}
__device__ __forceinline__ void ldsm4(uint32_t* r, uint32_t addr) {
    asm volatile("ldmatrix.sync.aligned.m8n8.x4.shared.b16 {%0,%1,%2,%3}, [%4];"
        : "=r"(r[0]), "=r"(r[1]), "=r"(r[2]), "=r"(r[3]) : "r"(addr));
}
__device__ __forceinline__ uint32_t smem_u32(const void* p) {
    uint32_t a;
    asm("{ .reg .u64 t; cvta.to.shared.u64 t, %1; cvt.u32.u64 %0, t; }" : "=r"(a) : "l"(p));
    return a;
}

// ---- smem rows: 64 halves = 128B, xor swizzle on 16B chunks ----
#define A_TILE 16384             // 128 rows
#define B_TILE 32768             // 256 rows
#define CV_SMEM (2 * A_TILE + 2 * B_TILE)   // conv: 2-stage, 96KB -> 2 CTA/SM
#define ST_SMEM (2 * A_TILE + 2 * B_TILE)   // stem: 2-stage, 96KB
#define PR_SMEM (4 * A_TILE)                // pred: 2-stage, 64KB (B=128 rows)

// One 64-deep K stage for one warp (tile 64x32), acc[4][4][4].
__device__ __forceinline__ void compute_stage(uint32_t abase, uint32_t bbase,
                                              int wm, int wn, int lane,
                                              float acc[4][4][4]) {
    const int ar = lane & 15, ac = lane >> 4;
    const int bn = (lane & 7) + ((lane >> 4) << 3);
    const int bk = (lane >> 3) & 1;
    #pragma unroll
    for (int ks = 0; ks < 4; ks++) {
        uint32_t a[4][4], b[2][4];
        #pragma unroll
        for (int i = 0; i < 4; i++) {
            int row = wm * 64 + i * 16 + ar;
            int ch  = (ks * 2 + ac) ^ (row & 7);
            ldsm4(a[i], abase + row * 128 + ch * 16);
        }
        #pragma unroll
        for (int j = 0; j < 2; j++) {
            int n  = wn * 32 + j * 16 + bn;
            int ch = (ks * 2 + bk) ^ (n & 7);
            ldsm4(b[j], bbase + n * 128 + ch * 16);
        }
        #pragma unroll
        for (int i = 0; i < 4; i++)
            #pragma unroll
            for (int jj = 0; jj < 4; jj++)
                mma16816(acc[i][jj], a[i], b[jj >> 1][(jj & 1) * 2], b[jj >> 1][(jj & 1) * 2 + 1]);
    }
}

// ================= Kernel 0: decode indices (int64/int32 autodetect) ========
__global__ void decode_indices(const int* __restrict__ idx32) {
    int n = blockIdx.x * blockDim.x + threadIdx.x;
    if (n >= NPTS) return;
    bool is64 = true;
    #pragma unroll
    for (int k = 1; k < 24; k += 2) is64 = is64 && (idx32[k] == 0);
    int bi, yi, xi;
    if (is64) { bi = idx32[6 * n]; yi = idx32[6 * n + 2]; xi = idx32[6 * n + 4]; }
    else      { bi = idx32[3 * n]; yi = idx32[3 * n + 1]; xi = idx32[3 * n + 2]; }
    g_sb[n] = bi; g_sy[n] = yi; g_sx[n] = xi;
}

// ================= prep kernels =================
__global__ void prep_x(const float* __restrict__ x) {
    __shared__ float t[32][33];
    int p0 = blockIdx.x * 32, c0 = blockIdx.y * 32, b = blockIdx.z;
    int tx = threadIdx.x, ty = threadIdx.y;
    #pragma unroll
    for (int j = 0; j < 4; j++) {
        int c = c0 + ty + j * 8;
        t[ty + j * 8][tx] = x[((size_t)b * CIN + c) * HW + p0 + tx];
    }
    __syncthreads();
    #pragma unroll
    for (int j = 0; j < 4; j++) {
        int p = p0 + ty + j * 8;
        g_x[((size_t)b * HW + p) * CIN + c0 + tx] = __float2half_rn(t[tx][ty + j * 8]);
    }
}

// Fused weight prep: conv W (perm+cvt), stem W (cvt), pred W2 (pad+cvt) + biases.
#define CW_N (512 * KD)          // 1179648
#define SW_N (CC * CIN)          // 65536
#define PW_N (128 * 512)         // 65536
__global__ void prep_weights(const float* __restrict__ wc, const float* __restrict__ wr,
                             const float* __restrict__ sw,
                             const float* __restrict__ cpw, const float* __restrict__ cpb,
                             const float* __restrict__ rpw, const float* __restrict__ rpb,
                             const float* __restrict__ opw, const float* __restrict__ opb) {
    int idx = blockIdx.x * blockDim.x + threadIdx.x;
    if (idx < CW_N) {
        int o = idx / KD, r = idx % KD;
        int q = r >> 8, c = r & 255;
        int korig = c * 9 + q;
        float v = (o < 256) ? wc[(size_t)o * KD + korig] : wr[(size_t)(o - 256) * KD + korig];
        g_cw[idx] = __float2half_rn(v);
        return;
    }
    int j = idx - CW_N;
    if (j < SW_N) { g_sw[j] = __float2half_rn(sw[j]); return; }
    j -= SW_N;
    if (j < PW_N) {
        int o = j >> 9, k = j & 511;
        float v = 0.f;
        if (o < 4)       { if (k >= 256) v = rpw[o * 256 + (k - 256)]; }
        else if (o == 4) { if (k >= 256) v = opw[k - 256]; }
        else if (o < 85) { if (k < 256)  v = cpw[(o - 5) * 256 + k]; }
        g_predw2[j] = __float2half_rn(v);
        if (k == 0) {
            float bv = 0.f;
            if (o < 4) bv = rpb[o]; else if (o == 4) bv = opb[0]; else if (o < 85) bv = cpb[o - 5];
            g_predb[o] = bv;
        }
    }
}

// ================= stem GEMM (fp16, 2-stage, N=256) =================
// grid 400, 512 thr (16 warps). M=128 pixels, N=256 outs, K=256 (4 stages).
__global__ __launch_bounds__(512) void stem_gemm(const float* __restrict__ bias) {
    extern __shared__ char sm[];
    uint32_t smb = smem_u32(sm);
    int tid = threadIdx.x, lane = tid & 31, wid = tid >> 5;
    int wm = wid & 1, wn = wid >> 1;    // wn 0..7
    int m0 = blockIdx.x * 128;

    float acc[4][4][4] = {};
    const int NCH = CIN / 64;   // 4

    auto load_stage = [&](int buf, int i) {
        int kc = i * 64;
        char* A = sm + buf * A_TILE;
        char* B = sm + 2 * A_TILE + buf * B_TILE;
        #pragma unroll
        for (int j2 = 0; j2 < 2; j2++) {
            int l = tid + 512 * j2;
            int row = l >> 3, ch = l & 7;
            int sw = (ch ^ (row & 7)) * 16 + row * 128;
            __pipeline_memcpy_async(A + sw, g_x + ((size_t)(m0 + row) * CIN + kc + ch * 8), 16);
        }
        #pragma unroll
        for (int j2 = 0; j2 < 4; j2++) {
            int l = tid + 512 * j2;
            int row = l >> 3, ch = l & 7;
            int sw = (ch ^ (row & 7)) * 16 + row * 128;
            __pipeline_memcpy_async(B + sw, g_sw + ((size_t)row * CIN + kc + ch * 8), 16);
        }
    };

    load_stage(0, 0); __pipeline_commit();
    for (int i = 0; i < NCH; i++) {
        __pipeline_wait_prior(0);
        __syncthreads();
        if (i + 1 < NCH) { load_stage((i + 1) & 1, i + 1); __pipeline_commit(); }
        compute_stage(smb + (i & 1) * A_TILE, smb + 2 * A_TILE + (i & 1) * B_TILE,
                      wm, wn, lane, acc);
    }

    int g = lane >> 2, tg = lane & 3;
    #pragma unroll
    for (int i = 0; i < 4; i++) {
        #pragma unroll
        for (int jj = 0; jj < 4; jj++) {
            int col = wn * 32 + jj * 8 + tg * 2;
            float b0 = bias[col], b1 = bias[col + 1];
            int r0 = m0 + wm * 64 + i * 16 + g;
            #pragma unroll
            for (int h = 0; h < 2; h++) {
                int pix = r0 + h * 8;
                __half2 hp;
                hp.x = __float2half_rn(silu(acc[i][jj][h * 2 + 0] + b0));
                hp.y = __float2half_rn(silu(acc[i][jj][h * 2 + 1] + b1));
                *(__half2*)&g_s[(size_t)pix * CC + col] = hp;
            }
        }
    }
}

// ================= conv GEMM (fp16, fused gather, 2-stage, occ-2) =====
// grid (128, 2), 512 thr (16 warps). M=128 pts, N=256 outs, K=2304 (36 stages).
__global__ __launch_bounds__(512) void conv_gemm(const float* __restrict__ bc,
                                                 const float* __restrict__ br) {
    extern __shared__ char sm[];
    __shared__ int ssb[128], ssy[128], ssx[128];
    uint32_t smb = smem_u32(sm);
    int tid = threadIdx.x, lane = tid & 31, wid = tid >> 5;
    int wm = wid & 1, wn = wid >> 1;       // wn 0..7
    int n0 = blockIdx.x * 128;
    int set = blockIdx.y;                  // 0=cls, 1=reg
    int oB = set * 256;

    if (tid < 128) { ssb[tid] = g_sb[n0 + tid]; ssy[tid] = g_sy[n0 + tid]; ssx[tid] = g_sx[n0 + tid]; }
    __syncthreads();

    float acc[4][4][4] = {};
    const int NCH = KD / 64;   // 36

    auto load_stage = [&](int buf, int i) {
        int kc = i * 64;
        int q = kc >> 8, c0 = kc & 255;
        int kh = q / 3, kw = q - kh * 3;
        char* A = sm + buf * A_TILE;
        char* B = sm + 2 * A_TILE + buf * B_TILE;
        #pragma unroll
        for (int j2 = 0; j2 < 2; j2++) {
            int l = tid + 512 * j2;
            int row = l >> 3, ch = l & 7;
            int sw = (ch ^ (row & 7)) * 16 + row * 128;
            int y = ssy[row] + kh - 1, xx = ssx[row] + kw - 1;
            bool ok = ((unsigned)y < (unsigned)NYv) && ((unsigned)xx < (unsigned)NXv);
            const __half* gp = g_s +
                ((((size_t)ssb[row] * NYv + (ok ? y : 0)) * NXv + (ok ? xx : 0)) * CC + c0 + ch * 8);
            __pipeline_memcpy_async(A + sw, gp, 16, ok ? 0 : 16);   // zfill when OOB
        }
        #pragma unroll
        for (int j2 = 0; j2 < 4; j2++) {
            int l = tid + 512 * j2;
            int row = l >> 3, ch = l & 7;
            int sw = (ch ^ (row & 7)) * 16 + row * 128;
            __pipeline_memcpy_async(B + sw, g_cw + ((size_t)(oB + row) * KD + kc + ch * 8), 16);
        }
    };

    load_stage(0, 0); __pipeline_commit();
    for (int i = 0; i < NCH; i++) {
        __pipeline_wait_prior(0);
        __syncthreads();
        if (i + 1 < NCH) { load_stage((i + 1) & 1, i + 1); __pipeline_commit(); }
        compute_stage(smb + (i & 1) * A_TILE, smb + 2 * A_TILE + (i & 1) * B_TILE,
                      wm, wn, lane, acc);
    }

    const float* bp = set ? br : bc;
    int g = lane >> 2, tg = lane & 3;
    #pragma unroll
    for (int i = 0; i < 4; i++) {
        #pragma unroll
        for (int jj = 0; jj < 4; jj++) {
            int col = wn * 32 + jj * 8 + tg * 2;      // 0..255 within set
            float b0 = bp[col], b1 = bp[col + 1];
            int r0 = n0 + wm * 64 + i * 16 + g;
            #pragma unroll
            for (int h = 0; h < 2; h++) {
                int n = r0 + h * 8;
                __half2 hp;
                hp.x = __float2half_rn(silu(acc[i][jj][h * 2 + 0] + b0));
                hp.y = __float2half_rn(silu(acc[i][jj][h * 2 + 1] + b1));
                *(__half2*)&g_featH[(size_t)n * 512 + set * 256 + col] = hp;
            }
        }
    }
}

// ================= pred GEMM (fp16 mma) =================
// grid 128, 256 thr (8 warps: 2x4). M=128 pts, N=128 (85 used), K=512 (8 stages).
__global__ __launch_bounds__(256) void pred_gemm(float* __restrict__ out) {
    extern __shared__ char sm[];
    uint32_t smb = smem_u32(sm);
    int tid = threadIdx.x, lane = tid & 31, wid = tid >> 5;
    int wm = wid & 1, wn = wid >> 1;    // wn 0..3
    int n0 = blockIdx.x * 128;

    float acc[4][4][4] = {};
    const int NCH = 512 / 64;   // 8

    auto load_stage = [&](int buf, int i) {
        int kc = i * 64;
        char* A = sm + buf * A_TILE;
        char* B = sm + 2 * A_TILE + buf * A_TILE;   // B tile 128 rows = 16KB
        #pragma unroll
        for (int j2 = 0; j2 < 4; j2++) {
            int l = tid + 256 * j2;
            int row = l >> 3, ch = l & 7;
            int sw = (ch ^ (row & 7)) * 16 + row * 128;
            __pipeline_memcpy_async(A + sw, g_featH + ((size_t)(n0 + row) * 512 + kc + ch * 8), 16);
            __pipeline_memcpy_async(B + sw, g_predw2 + ((size_t)row * 512 + kc + ch * 8), 16);
        }
    };

    load_stage(0, 0); __pipeline_commit();
    for (int i = 0; i < NCH; i++) {
        __pipeline_wait_prior(0);
        __syncthreads();
        if (i + 1 < NCH) { load_stage((i + 1) & 1, i + 1); __pipeline_commit(); }
        compute_stage(smb + (i & 1) * A_TILE, smb + 2 * A_TILE + (i & 1) * A_TILE,
                      wm, wn, lane, acc);
    }

    int g = lane >> 2, tg = lane & 3;
    #pragma unroll
    for (int i = 0; i < 4; i++) {
        #pragma unroll
        for (int jj = 0; jj < 4; jj++) {
            int col = wn * 32 + jj * 8 + tg * 2;     // 0..127
            int r0 = n0 + wm * 64 + i * 16 + g;
            if (col < NOUT) {
                float bv = g_predb[col];
                out[(size_t)r0 * NOUT + col]       = acc[i][jj][0] + bv;
                out[(size_t)(r0 + 8) * NOUT + col] = acc[i][jj][2] + bv;
            }
            if (col + 1 < NOUT) {
                float bv = g_predb[col + 1];
                out[(size_t)r0 * NOUT + col + 1]       = acc[i][jj][1] + bv;
                out[(size_t)(r0 + 8) * NOUT + col + 1] = acc[i][jj][3] + bv;
            }
        }
    }
}

// ================= launch =================
extern "C" void kernel_launch(void* const* d_in, const int* in_sizes, int n_in,
                              void* d_out, int out_size) {
    const float* x          = (const float*)d_in[0];
    const int*   indices32  = (const int*)d_in[1];
    const float* stem_w     = (const float*)d_in[2];
    const float* stem_b     = (const float*)d_in[3];
    const float* cls_conv_w = (const float*)d_in[4];
    const float* cls_conv_b = (const float*)d_in[5];
    const float* reg_conv_w = (const float*)d_in[6];
    const float* reg_conv_b = (const float*)d_in[7];
    const float* cls_pred_w = (const float*)d_in[8];
    const float* cls_pred_b = (const float*)d_in[9];
    const float* reg_pred_w = (const float*)d_in[10];
    const float* reg_pred_b = (const float*)d_in[11];
    const float* obj_pred_w = (const float*)d_in[12];
    const float* obj_pred_b = (const float*)d_in[13];
    float* out = (float*)d_out;

    cudaFuncSetAttribute(stem_gemm, cudaFuncAttributeMaxDynamicSharedMemorySize, ST_SMEM);
    cudaFuncSetAttribute(conv_gemm, cudaFuncAttributeMaxDynamicSharedMemorySize, CV_SMEM);
    cudaFuncSetAttribute(pred_gemm, cudaFuncAttributeMaxDynamicSharedMemorySize, PR_SMEM);

    decode_indices<<<NPTS / 256, 256>>>(indices32);

    dim3 gx(HW / 32, CIN / 32, BSZ);
    prep_x<<<gx, dim3(32, 8)>>>(x);
    prep_weights<<<(CW_N + SW_N + PW_N + 255) / 256, 256>>>(
        cls_conv_w, reg_conv_w, stem_w,
        cls_pred_w, cls_pred_b, reg_pred_w, reg_pred_b, obj_pred_w, obj_pred_b);

    stem_gemm<<<NPIX / 128, 512, ST_SMEM>>>(stem_b);
    conv_gemm<<<dim3(NPTS / 128, 2), 512, CV_SMEM>>>(cls_conv_b, reg_conv_b);
    pred_gemm<<<NPTS / 128, 256, PR_SMEM>>>(out);
}